// round 9
// baseline (speedup 1.0000x reference)
#include <cuda_runtime.h>
#include <math.h>
#include <stdint.h>

#define B_  4
#define S_  2048
#define D_  2048
#define H_  16
#define DH_ 128
#define M_  (B_*S_)

// Scratch (allowed: __device__ globals)
__device__ float g_q[(size_t)B_*H_*S_*DH_];
__device__ float g_k[(size_t)B_*H_*S_*DH_];
__device__ float g_v[(size_t)B_*H_*S_*DH_];
__device__ float g_ctx[(size_t)B_*S_*D_];
__device__ float g_cos[(size_t)S_*64];
__device__ float g_sin[(size_t)S_*64];

// ---------------------------------------------------------------------------
// TF32 helpers
// ---------------------------------------------------------------------------
__device__ __forceinline__ uint32_t tf32u(float x) {
    uint32_t r;
    asm("cvt.rna.tf32.f32 %0, %1;" : "=r"(r) : "f"(x));
    return r;
}
__device__ __forceinline__ float f2tf32(float x) { return __uint_as_float(tf32u(x)); }

__device__ __forceinline__ void mma_tf32(float c[4], const uint32_t a[4], const uint32_t b[2]) {
    asm volatile(
        "mma.sync.aligned.m16n8k8.row.col.f32.tf32.tf32.f32 "
        "{%0,%1,%2,%3}, {%4,%5,%6,%7}, {%8,%9}, {%0,%1,%2,%3};"
        : "+f"(c[0]), "+f"(c[1]), "+f"(c[2]), "+f"(c[3])
        : "r"(a[0]), "r"(a[1]), "r"(a[2]), "r"(a[3]), "r"(b[0]), "r"(b[1]));
}

// ---------------------------------------------------------------------------
// TF32 tensor-core GEMM (R6-proven): C = A·Wᵀ + bias
// 128x128 block, 128 threads (4 warps, 2x2), 64x64 warp tile, double-buffered.
// ---------------------------------------------------------------------------
template<bool HEADS>
__global__ __launch_bounds__(128)
void gemm_tf32(const float* __restrict__ A, const float* __restrict__ W,
               const float* __restrict__ bias, float* __restrict__ C)
{
    __shared__ float As[2][128][20];
    __shared__ float Ws[2][128][20];
    const int K  = D_;
    const int m0 = blockIdx.y * 128;
    const int n0 = blockIdx.x * 128;
    const int tid  = threadIdx.x;
    const int warp = tid >> 5, lane = tid & 31;
    const int wy = warp >> 1, wx = warp & 1;
    const int lr = lane >> 2, lc = lane & 3;

    float acc[4][8][4];
#pragma unroll
    for (int ti = 0; ti < 4; ti++)
#pragma unroll
        for (int nt = 0; nt < 8; nt++)
#pragma unroll
            for (int e = 0; e < 4; e++) acc[ti][nt][e] = 0.f;

    float4 pa[4], pw[4];
#pragma unroll
    for (int u = 0; u < 4; u++) {
        const int f = tid + u * 128;
        const int r = f >> 2, c4 = f & 3;
        pa[u] = *(const float4*)(A + (size_t)(m0 + r) * K + c4 * 4);
        pw[u] = *(const float4*)(W + (size_t)(n0 + r) * K + c4 * 4);
    }
#pragma unroll
    for (int u = 0; u < 4; u++) {
        const int f = tid + u * 128;
        const int r = f >> 2, c4 = f & 3;
        float4 av = pa[u];
        av.x = f2tf32(av.x); av.y = f2tf32(av.y);
        av.z = f2tf32(av.z); av.w = f2tf32(av.w);
        *(float4*)(&As[0][r][c4 * 4]) = av;
        float4 wv = pw[u];
        wv.x = f2tf32(wv.x); wv.y = f2tf32(wv.y);
        wv.z = f2tf32(wv.z); wv.w = f2tf32(wv.w);
        *(float4*)(&Ws[0][r][c4 * 4]) = wv;
    }

    const int NIT = K / 16;
    for (int it = 0; it < NIT; it++) {
        __syncthreads();
        const int cur = it & 1;
        const bool more = (it + 1 < NIT);
        if (more) {
            const int k0 = (it + 1) * 16;
#pragma unroll
            for (int u = 0; u < 4; u++) {
                const int f = tid + u * 128;
                const int r = f >> 2, c4 = f & 3;
                pa[u] = *(const float4*)(A + (size_t)(m0 + r) * K + k0 + c4 * 4);
                pw[u] = *(const float4*)(W + (size_t)(n0 + r) * K + k0 + c4 * 4);
            }
        }

#pragma unroll
        for (int kk = 0; kk < 16; kk += 8) {
            uint32_t afr[4][4], bfr[8][2];
            const int ac = kk + lc;
#pragma unroll
            for (int ti = 0; ti < 4; ti++) {
                const int ar = wy * 64 + ti * 16 + lr;
                afr[ti][0] = __float_as_uint(As[cur][ar    ][ac]);
                afr[ti][1] = __float_as_uint(As[cur][ar + 8][ac]);
                afr[ti][2] = __float_as_uint(As[cur][ar    ][ac + 4]);
                afr[ti][3] = __float_as_uint(As[cur][ar + 8][ac + 4]);
            }
#pragma unroll
            for (int nt = 0; nt < 8; nt++) {
                const int br = wx * 64 + nt * 8 + lr;
                bfr[nt][0] = __float_as_uint(Ws[cur][br][ac]);
                bfr[nt][1] = __float_as_uint(Ws[cur][br][ac + 4]);
            }
#pragma unroll
            for (int ti = 0; ti < 4; ti++)
#pragma unroll
                for (int nt = 0; nt < 8; nt++)
                    mma_tf32(acc[ti][nt], afr[ti], bfr[nt]);
        }

        if (more) {
            const int nxt = cur ^ 1;
#pragma unroll
            for (int u = 0; u < 4; u++) {
                const int f = tid + u * 128;
                const int r = f >> 2, c4 = f & 3;
                float4 av = pa[u];
                av.x = f2tf32(av.x); av.y = f2tf32(av.y);
                av.z = f2tf32(av.z); av.w = f2tf32(av.w);
                *(float4*)(&As[nxt][r][c4 * 4]) = av;
                float4 wv = pw[u];
                wv.x = f2tf32(wv.x); wv.y = f2tf32(wv.y);
                wv.z = f2tf32(wv.z); wv.w = f2tf32(wv.w);
                *(float4*)(&Ws[nxt][r][c4 * 4]) = wv;
            }
        }
    }

#pragma unroll
    for (int ti = 0; ti < 4; ti++) {
#pragma unroll
        for (int nt = 0; nt < 8; nt++) {
            const int row = m0 + wy * 64 + ti * 16 + lr;
            const int col = n0 + wx * 64 + nt * 8 + lc * 2;
#pragma unroll
            for (int e = 0; e < 4; e++) {
                const int m = row + (e >> 1) * 8;
                const int n = col + (e & 1);
                const float v = acc[ti][nt][e] + bias[n];
                if (HEADS) {
                    const int bb = m >> 11, s = m & (S_ - 1);
                    const int h = n >> 7, dh = n & 127;
                    C[(((size_t)bb * H_ + h) * S_ + s) * DH_ + dh] = v;
                } else {
                    C[(size_t)m * D_ + n] = v;
                }
            }
        }
    }
}

// ---------------------------------------------------------------------------
// RoPE table + fused q/k apply
// ---------------------------------------------------------------------------
__global__ __launch_bounds__(256)
void rope_table_kernel()
{
    const int idx = blockIdx.x * blockDim.x + threadIdx.x;
    const int p = idx & 63;
    const int s = idx >> 6;
    const float invf = (float)exp(-(double)p * (log(10000.0) / 64.0));
    const float ang  = (float)s * invf;
    g_cos[idx] = (float)cos((double)ang);
    g_sin[idx] = (float)sin((double)ang);
}

__global__ __launch_bounds__(256)
void rope_apply2_kernel()
{
    const int idx = blockIdx.x * blockDim.x + threadIdx.x;  // B*H*S*64
    const int p   = idx & 63;
    const int row = idx >> 6;
    const int s   = row & (S_ - 1);

    const float cs = g_cos[s * 64 + p];
    const float sn = g_sin[s * 64 + p];

    float* qb = g_q + (size_t)row * DH_;
    float* kb = g_k + (size_t)row * DH_;
    const float q1 = qb[p], q2 = qb[p + 64];
    qb[p]      = q1 * cs - q2 * sn;
    qb[p + 64] = q2 * cs + q1 * sn;
    const float k1 = kb[p], k2 = kb[p + 64];
    kb[p]      = k1 * cs - k2 * sn;
    kb[p + 64] = k2 * cs + k1 * sn;
}

// ---------------------------------------------------------------------------
// TF32 tensor-core flash attention, retiled: 128 q-rows/CTA, 4 warps,
// 32 q-rows/warp (two stacked m16 tiles), 64-key KV tiles, Q smem-resident.
// ---------------------------------------------------------------------------
#define QPAD 132
#define KPAD 132
#define VPAD 68
#define PPAD 76
#define SMEM_ATTN ((128*QPAD + 64*KPAD + 128*VPAD + 128*PPAD) * 4)

__global__ __launch_bounds__(128)
void attn_mma(float* __restrict__ ctx)
{
    extern __shared__ float sm[];
    float* Qs = sm;                                        // [128][QPAD]
    float* Ks = Qs + 128 * QPAD;                           // [64][KPAD]
    float* Vt = Ks + 64 * KPAD;                            // [128][VPAD]
    float* Ps = Vt + 128 * VPAD;                           // [128][PPAD]

    const int bh  = blockIdx.y;
    const int m0  = blockIdx.x * 128;
    const int tid = threadIdx.x;
    const int warp = tid >> 5, lane = tid & 31;
    const int lr = lane >> 2, lc = lane & 3;
    const int qr = warp * 32;

    const float* Qb = g_q + (size_t)bh * S_ * DH_;
    const float* Kb = g_k + (size_t)bh * S_ * DH_;
    const float* Vb = g_v + (size_t)bh * S_ * DH_;

    // ---- stage scaled Q (tf32) into Qs, persists all tiles ----
    const float scale = 0.08838834764831845f;   // 1/sqrt(128)
#pragma unroll
    for (int i = 0; i < 32; i++) {
        const int idx = tid + i * 128;
        const int r = idx >> 5, c4 = idx & 31;
        float4 v = *(const float4*)(Qb + (size_t)(m0 + r) * DH_ + c4 * 4);
        v.x = f2tf32(v.x * scale); v.y = f2tf32(v.y * scale);
        v.z = f2tf32(v.z * scale); v.w = f2tf32(v.w * scale);
        *(float4*)(&Qs[r * QPAD + c4 * 4]) = v;
    }

    float oacc[2][16][4];
#pragma unroll
    for (int ti = 0; ti < 2; ti++)
#pragma unroll
        for (int nt = 0; nt < 16; nt++)
#pragma unroll
            for (int e = 0; e < 4; e++) oacc[ti][nt][e] = 0.f;
    float mr[4] = {-1e30f, -1e30f, -1e30f, -1e30f};
    float ls[4] = {0.f, 0.f, 0.f, 0.f};

    for (int kt = 0; kt < 32; kt++) {
        __syncthreads();   // prev tile consumed (first iter: Q staging visible)
        const int key0 = kt * 64;
        // K tile: key-major, tf32
#pragma unroll
        for (int i = 0; i < 16; i++) {
            const int idx = tid + i * 128;
            const int r = idx >> 5, c4 = idx & 31;
            float4 v = *(const float4*)(Kb + (size_t)(key0 + r) * DH_ + c4 * 4);
            v.x = f2tf32(v.x); v.y = f2tf32(v.y);
            v.z = f2tf32(v.z); v.w = f2tf32(v.w);
            *(float4*)(&Ks[r * KPAD + c4 * 4]) = v;
        }
        // V tile transposed: Vt[d][key]
#pragma unroll
        for (int i = 0; i < 16; i++) {
            const int idx = tid + i * 128;
            const int d4 = idx >> 6, key = idx & 63;
            float4 v = *(const float4*)(Vb + (size_t)(key0 + key) * DH_ + d4 * 4);
            Vt[(d4 * 4 + 0) * VPAD + key] = f2tf32(v.x);
            Vt[(d4 * 4 + 1) * VPAD + key] = f2tf32(v.y);
            Vt[(d4 * 4 + 2) * VPAD + key] = f2tf32(v.z);
            Vt[(d4 * 4 + 3) * VPAD + key] = f2tf32(v.w);
        }
        __syncthreads();

        // ---- S = Q·Kᵀ : 32 q-rows (ti=0,1) x 64 keys ----
        float sacc[2][8][4];
#pragma unroll
        for (int ti = 0; ti < 2; ti++)
#pragma unroll
            for (int n = 0; n < 8; n++)
#pragma unroll
                for (int e = 0; e < 4; e++) sacc[ti][n][e] = 0.f;
#pragma unroll
        for (int ks = 0; ks < 16; ks++) {
            uint32_t a0[4], a1[4];
            const int c = ks * 8 + lc;
            a0[0] = __float_as_uint(Qs[(qr + lr     ) * QPAD + c    ]);
            a0[1] = __float_as_uint(Qs[(qr + lr +  8) * QPAD + c    ]);
            a0[2] = __float_as_uint(Qs[(qr + lr     ) * QPAD + c + 4]);
            a0[3] = __float_as_uint(Qs[(qr + lr +  8) * QPAD + c + 4]);
            a1[0] = __float_as_uint(Qs[(qr + lr + 16) * QPAD + c    ]);
            a1[1] = __float_as_uint(Qs[(qr + lr + 24) * QPAD + c    ]);
            a1[2] = __float_as_uint(Qs[(qr + lr + 16) * QPAD + c + 4]);
            a1[3] = __float_as_uint(Qs[(qr + lr + 24) * QPAD + c + 4]);
#pragma unroll
            for (int n = 0; n < 8; n++) {
                uint32_t b[2];
                b[0] = __float_as_uint(Ks[(n * 8 + lr) * KPAD + c    ]);
                b[1] = __float_as_uint(Ks[(n * 8 + lr) * KPAD + c + 4]);
                mma_tf32(sacc[0][n], a0, b);
                mma_tf32(sacc[1][n], a1, b);
            }
        }

        // ---- online softmax (4 row-groups: g = ti*2 + (e>>1)) ----
        float mx[4] = {mr[0], mr[1], mr[2], mr[3]};
#pragma unroll
        for (int ti = 0; ti < 2; ti++)
#pragma unroll
            for (int n = 0; n < 8; n++) {
                mx[ti*2    ] = fmaxf(mx[ti*2    ], fmaxf(sacc[ti][n][0], sacc[ti][n][1]));
                mx[ti*2 + 1] = fmaxf(mx[ti*2 + 1], fmaxf(sacc[ti][n][2], sacc[ti][n][3]));
            }
        float f[4];
#pragma unroll
        for (int g = 0; g < 4; g++) {
            mx[g] = fmaxf(mx[g], __shfl_xor_sync(0xffffffffu, mx[g], 1));
            mx[g] = fmaxf(mx[g], __shfl_xor_sync(0xffffffffu, mx[g], 2));
            f[g] = __expf(mr[g] - mx[g]);
            mr[g] = mx[g];
        }

        float srow[4] = {0.f, 0.f, 0.f, 0.f};
#pragma unroll
        for (int ti = 0; ti < 2; ti++)
#pragma unroll
            for (int n = 0; n < 8; n++) {
                const float p0 = __expf(sacc[ti][n][0] - mx[ti*2]);
                const float p1 = __expf(sacc[ti][n][1] - mx[ti*2]);
                const float p2 = __expf(sacc[ti][n][2] - mx[ti*2+1]);
                const float p3 = __expf(sacc[ti][n][3] - mx[ti*2+1]);
                srow[ti*2]   += p0 + p1;
                srow[ti*2+1] += p2 + p3;
                float2 lo; lo.x = f2tf32(p0); lo.y = f2tf32(p1);
                *(float2*)(&Ps[(qr + ti*16 + lr    ) * PPAD + n * 8 + lc * 2]) = lo;
                float2 hi; hi.x = f2tf32(p2); hi.y = f2tf32(p3);
                *(float2*)(&Ps[(qr + ti*16 + lr + 8) * PPAD + n * 8 + lc * 2]) = hi;
            }
#pragma unroll
        for (int g = 0; g < 4; g++) {
            srow[g] += __shfl_xor_sync(0xffffffffu, srow[g], 1);
            srow[g] += __shfl_xor_sync(0xffffffffu, srow[g], 2);
            ls[g] = ls[g] * f[g] + srow[g];
        }
#pragma unroll
        for (int ti = 0; ti < 2; ti++)
#pragma unroll
            for (int nt = 0; nt < 16; nt++) {
                oacc[ti][nt][0] *= f[ti*2];   oacc[ti][nt][1] *= f[ti*2];
                oacc[ti][nt][2] *= f[ti*2+1]; oacc[ti][nt][3] *= f[ti*2+1];
            }
        __syncwarp();  // own-warp P stores before P fragment loads

        // ---- O += P·V ----
#pragma unroll
        for (int kk = 0; kk < 8; kk++) {
            uint32_t a0[4], a1[4];
            const int c = kk * 8 + lc;
            a0[0] = __float_as_uint(Ps[(qr + lr     ) * PPAD + c    ]);
            a0[1] = __float_as_uint(Ps[(qr + lr +  8) * PPAD + c    ]);
            a0[2] = __float_as_uint(Ps[(qr + lr     ) * PPAD + c + 4]);
            a0[3] = __float_as_uint(Ps[(qr + lr +  8) * PPAD + c + 4]);
            a1[0] = __float_as_uint(Ps[(qr + lr + 16) * PPAD + c    ]);
            a1[1] = __float_as_uint(Ps[(qr + lr + 24) * PPAD + c    ]);
            a1[2] = __float_as_uint(Ps[(qr + lr + 16) * PPAD + c + 4]);
            a1[3] = __float_as_uint(Ps[(qr + lr + 24) * PPAD + c + 4]);
#pragma unroll
            for (int nt = 0; nt < 16; nt++) {
                uint32_t b[2];
                b[0] = __float_as_uint(Vt[(nt * 8 + lr) * VPAD + c    ]);
                b[1] = __float_as_uint(Vt[(nt * 8 + lr) * VPAD + c + 4]);
                mma_tf32(oacc[0][nt], a0, b);
                mma_tf32(oacc[1][nt], a1, b);
            }
        }
    }

    // ---- epilogue: normalize + scatter to ctx[b][s][h*128+d] ----
    float inv[4];
#pragma unroll
    for (int g = 0; g < 4; g++) inv[g] = 1.f / ls[g];
    const int bb = bh >> 4, h = bh & 15;
#pragma unroll
    for (int ti = 0; ti < 2; ti++) {
        const int gr = m0 + qr + ti * 16 + lr;
        float* o0 = ctx + ((size_t)bb * S_ + gr) * D_ + h * DH_;
        float* o1 = o0 + (size_t)8 * D_;
        const float i0 = inv[ti*2], i1 = inv[ti*2+1];
#pragma unroll
        for (int nt = 0; nt < 16; nt++) {
            float2 a; a.x = oacc[ti][nt][0] * i0; a.y = oacc[ti][nt][1] * i0;
            *(float2*)(o0 + nt * 8 + lc * 2) = a;
            float2 b; b.x = oacc[ti][nt][2] * i1; b.y = oacc[ti][nt][3] * i1;
            *(float2*)(o1 + nt * 8 + lc * 2) = b;
        }
    }
}

// ---------------------------------------------------------------------------
extern "C" void kernel_launch(void* const* d_in, const int* in_sizes, int n_in,
                              void* d_out, int out_size)
{
    const float* x  = (const float*)d_in[0];
    const float* wq = (const float*)d_in[1];
    const float* bq = (const float*)d_in[2];
    const float* wk = (const float*)d_in[3];
    const float* bk = (const float*)d_in[4];
    const float* wv = (const float*)d_in[5];
    const float* bv = (const float*)d_in[6];
    const float* wo = (const float*)d_in[7];
    const float* bo = (const float*)d_in[8];
    float* out = (float*)d_out;

    float *q, *k, *v, *ctx;
    cudaGetSymbolAddress((void**)&q,   g_q);
    cudaGetSymbolAddress((void**)&k,   g_k);
    cudaGetSymbolAddress((void**)&v,   g_v);
    cudaGetSymbolAddress((void**)&ctx, g_ctx);

    cudaFuncSetAttribute(attn_mma, cudaFuncAttributeMaxDynamicSharedMemorySize, SMEM_ATTN);

    const dim3 ggrid(D_ / 128, M_ / 128);   // (16, 64)

    rope_table_kernel<<<(S_ * 64) / 256, 256>>>();

    gemm_tf32<true><<<ggrid, 128>>>(x, wq, bq, q);
    gemm_tf32<true><<<ggrid, 128>>>(x, wk, bk, k);
    gemm_tf32<true><<<ggrid, 128>>>(x, wv, bv, v);

    const int rope_threads = B_ * H_ * S_ * 64;
    rope_apply2_kernel<<<rope_threads / 256, 256>>>();

    attn_mma<<<dim3(S_ / 128, B_ * H_), 128, SMEM_ATTN>>>(ctx);

    gemm_tf32<false><<<ggrid, 128>>>(ctx, wo, bo, out);
}

// round 10
// speedup vs baseline: 1.5871x; 1.5871x over previous
#include <cuda_runtime.h>
#include <math.h>
#include <stdint.h>

#define B_  4
#define S_  2048
#define D_  2048
#define H_  16
#define DH_ 128
#define M_  (B_*S_)

// Scratch (allowed: __device__ globals)
__device__ float g_q[(size_t)B_*H_*S_*DH_];
__device__ float g_k[(size_t)B_*H_*S_*DH_];
__device__ float g_v[(size_t)B_*H_*S_*DH_];
__device__ float g_ctx[(size_t)B_*S_*D_];
__device__ float g_cos[(size_t)S_*64];
__device__ float g_sin[(size_t)S_*64];

// ---------------------------------------------------------------------------
// TF32 helpers
// ---------------------------------------------------------------------------
__device__ __forceinline__ uint32_t tf32u(float x) {
    uint32_t r;
    asm("cvt.rna.tf32.f32 %0, %1;" : "=r"(r) : "f"(x));
    return r;
}
__device__ __forceinline__ float f2tf32(float x) { return __uint_as_float(tf32u(x)); }

__device__ __forceinline__ void mma_tf32(float c[4], const uint32_t a[4], const uint32_t b[2]) {
    asm volatile(
        "mma.sync.aligned.m16n8k8.row.col.f32.tf32.tf32.f32 "
        "{%0,%1,%2,%3}, {%4,%5,%6,%7}, {%8,%9}, {%0,%1,%2,%3};"
        : "+f"(c[0]), "+f"(c[1]), "+f"(c[2]), "+f"(c[3])
        : "r"(a[0]), "r"(a[1]), "r"(a[2]), "r"(a[3]), "r"(b[0]), "r"(b[1]));
}

// ---------------------------------------------------------------------------
// TF32 tensor-core GEMM (R6-proven): C = A·Wᵀ + bias
// 128x128 block, 128 threads (4 warps, 2x2), 64x64 warp tile, double-buffered.
// ---------------------------------------------------------------------------
template<bool HEADS>
__global__ __launch_bounds__(128)
void gemm_tf32(const float* __restrict__ A, const float* __restrict__ W,
               const float* __restrict__ bias, float* __restrict__ C)
{
    __shared__ float As[2][128][20];
    __shared__ float Ws[2][128][20];
    const int K  = D_;
    const int m0 = blockIdx.y * 128;
    const int n0 = blockIdx.x * 128;
    const int tid  = threadIdx.x;
    const int warp = tid >> 5, lane = tid & 31;
    const int wy = warp >> 1, wx = warp & 1;
    const int lr = lane >> 2, lc = lane & 3;

    float acc[4][8][4];
#pragma unroll
    for (int ti = 0; ti < 4; ti++)
#pragma unroll
        for (int nt = 0; nt < 8; nt++)
#pragma unroll
            for (int e = 0; e < 4; e++) acc[ti][nt][e] = 0.f;

    float4 pa[4], pw[4];
#pragma unroll
    for (int u = 0; u < 4; u++) {
        const int f = tid + u * 128;
        const int r = f >> 2, c4 = f & 3;
        pa[u] = *(const float4*)(A + (size_t)(m0 + r) * K + c4 * 4);
        pw[u] = *(const float4*)(W + (size_t)(n0 + r) * K + c4 * 4);
    }
#pragma unroll
    for (int u = 0; u < 4; u++) {
        const int f = tid + u * 128;
        const int r = f >> 2, c4 = f & 3;
        float4 av = pa[u];
        av.x = f2tf32(av.x); av.y = f2tf32(av.y);
        av.z = f2tf32(av.z); av.w = f2tf32(av.w);
        *(float4*)(&As[0][r][c4 * 4]) = av;
        float4 wv = pw[u];
        wv.x = f2tf32(wv.x); wv.y = f2tf32(wv.y);
        wv.z = f2tf32(wv.z); wv.w = f2tf32(wv.w);
        *(float4*)(&Ws[0][r][c4 * 4]) = wv;
    }

    const int NIT = K / 16;
    for (int it = 0; it < NIT; it++) {
        __syncthreads();
        const int cur = it & 1;
        const bool more = (it + 1 < NIT);
        if (more) {
            const int k0 = (it + 1) * 16;
#pragma unroll
            for (int u = 0; u < 4; u++) {
                const int f = tid + u * 128;
                const int r = f >> 2, c4 = f & 3;
                pa[u] = *(const float4*)(A + (size_t)(m0 + r) * K + k0 + c4 * 4);
                pw[u] = *(const float4*)(W + (size_t)(n0 + r) * K + k0 + c4 * 4);
            }
        }

#pragma unroll
        for (int kk = 0; kk < 16; kk += 8) {
            uint32_t afr[4][4], bfr[8][2];
            const int ac = kk + lc;
#pragma unroll
            for (int ti = 0; ti < 4; ti++) {
                const int ar = wy * 64 + ti * 16 + lr;
                afr[ti][0] = __float_as_uint(As[cur][ar    ][ac]);
                afr[ti][1] = __float_as_uint(As[cur][ar + 8][ac]);
                afr[ti][2] = __float_as_uint(As[cur][ar    ][ac + 4]);
                afr[ti][3] = __float_as_uint(As[cur][ar + 8][ac + 4]);
            }
#pragma unroll
            for (int nt = 0; nt < 8; nt++) {
                const int br = wx * 64 + nt * 8 + lr;
                bfr[nt][0] = __float_as_uint(Ws[cur][br][ac]);
                bfr[nt][1] = __float_as_uint(Ws[cur][br][ac + 4]);
            }
#pragma unroll
            for (int ti = 0; ti < 4; ti++)
#pragma unroll
                for (int nt = 0; nt < 8; nt++)
                    mma_tf32(acc[ti][nt], afr[ti], bfr[nt]);
        }

        if (more) {
            const int nxt = cur ^ 1;
#pragma unroll
            for (int u = 0; u < 4; u++) {
                const int f = tid + u * 128;
                const int r = f >> 2, c4 = f & 3;
                float4 av = pa[u];
                av.x = f2tf32(av.x); av.y = f2tf32(av.y);
                av.z = f2tf32(av.z); av.w = f2tf32(av.w);
                *(float4*)(&As[nxt][r][c4 * 4]) = av;
                float4 wv = pw[u];
                wv.x = f2tf32(wv.x); wv.y = f2tf32(wv.y);
                wv.z = f2tf32(wv.z); wv.w = f2tf32(wv.w);
                *(float4*)(&Ws[nxt][r][c4 * 4]) = wv;
            }
        }
    }

#pragma unroll
    for (int ti = 0; ti < 4; ti++) {
#pragma unroll
        for (int nt = 0; nt < 8; nt++) {
            const int row = m0 + wy * 64 + ti * 16 + lr;
            const int col = n0 + wx * 64 + nt * 8 + lc * 2;
#pragma unroll
            for (int e = 0; e < 4; e++) {
                const int m = row + (e >> 1) * 8;
                const int n = col + (e & 1);
                const float v = acc[ti][nt][e] + bias[n];
                if (HEADS) {
                    const int bb = m >> 11, s = m & (S_ - 1);
                    const int h = n >> 7, dh = n & 127;
                    C[(((size_t)bb * H_ + h) * S_ + s) * DH_ + dh] = v;
                } else {
                    C[(size_t)m * D_ + n] = v;
                }
            }
        }
    }
}

// ---------------------------------------------------------------------------
// RoPE table + fused q/k apply (single streaming pass)
// ---------------------------------------------------------------------------
__global__ __launch_bounds__(256)
void rope_table_kernel()
{
    const int idx = blockIdx.x * blockDim.x + threadIdx.x;
    const int p = idx & 63;
    const int s = idx >> 6;
    const float invf = (float)exp(-(double)p * (log(10000.0) / 64.0));
    const float ang  = (float)s * invf;
    g_cos[idx] = (float)cos((double)ang);
    g_sin[idx] = (float)sin((double)ang);
}

__global__ __launch_bounds__(256)
void rope_apply2_kernel()
{
    const int idx = blockIdx.x * blockDim.x + threadIdx.x;  // B*H*S*64
    const int p   = idx & 63;
    const int row = idx >> 6;
    const int s   = row & (S_ - 1);

    const float cs = g_cos[s * 64 + p];
    const float sn = g_sin[s * 64 + p];

    float* qb = g_q + (size_t)row * DH_;
    float* kb = g_k + (size_t)row * DH_;
    const float q1 = qb[p], q2 = qb[p + 64];
    qb[p]      = q1 * cs - q2 * sn;
    qb[p + 64] = q2 * cs + q1 * sn;
    const float k1 = kb[p], k2 = kb[p + 64];
    kb[p]      = k1 * cs - k2 * sn;
    kb[p + 64] = k2 * cs + k1 * sn;
}

// ---------------------------------------------------------------------------
// TF32 tensor-core flash attention (R3-proven): 64 q-rows/CTA, 4 warps,
// 16 q-rows/warp, Q register-resident, 88KB smem -> 2 CTAs/SM.
// ---------------------------------------------------------------------------
#define KPAD 132
#define VPAD 68
#define PPAD 76
#define SMEM_ATTN ((64*KPAD + 128*VPAD + 64*PPAD) * 4)

__global__ __launch_bounds__(128)
void attn_mma(float* __restrict__ ctx)
{
    extern __shared__ float sm[];
    float* Ks = sm;
    float* Vt = sm + 64 * KPAD;
    float* Ps = sm + 64 * KPAD + 128 * VPAD;

    const int bh  = blockIdx.y;
    const int m0  = blockIdx.x * 64;
    const int tid = threadIdx.x;
    const int warp = tid >> 5, lane = tid & 31;
    const int lr = lane >> 2, lc = lane & 3;
    const int qr = warp * 16;

    const float* Qb = g_q + (size_t)bh * S_ * DH_;
    const float* Kb = g_k + (size_t)bh * S_ * DH_;
    const float* Vb = g_v + (size_t)bh * S_ * DH_;

    const float scale = 0.08838834764831845f;
#pragma unroll
    for (int i = 0; i < 16; i++) {
        const int idx = tid + i * 128;
        const int r = idx >> 5, c4 = idx & 31;
        float4 v = *(const float4*)(Qb + (size_t)(m0 + r) * DH_ + c4 * 4);
        v.x = f2tf32(v.x * scale); v.y = f2tf32(v.y * scale);
        v.z = f2tf32(v.z * scale); v.w = f2tf32(v.w * scale);
        *(float4*)(&Ks[r * KPAD + c4 * 4]) = v;
    }
    __syncthreads();
    uint32_t qf[16][4];
#pragma unroll
    for (int ks = 0; ks < 16; ks++) {
        qf[ks][0] = __float_as_uint(Ks[(qr + lr    ) * KPAD + ks * 8 + lc    ]);
        qf[ks][1] = __float_as_uint(Ks[(qr + lr + 8) * KPAD + ks * 8 + lc    ]);
        qf[ks][2] = __float_as_uint(Ks[(qr + lr    ) * KPAD + ks * 8 + lc + 4]);
        qf[ks][3] = __float_as_uint(Ks[(qr + lr + 8) * KPAD + ks * 8 + lc + 4]);
    }

    float oacc[16][4];
#pragma unroll
    for (int nt = 0; nt < 16; nt++)
#pragma unroll
        for (int e = 0; e < 4; e++) oacc[nt][e] = 0.f;
    float mr0 = -1e30f, mr1 = -1e30f, lsum0 = 0.f, lsum1 = 0.f;

    for (int kt = 0; kt < 32; kt++) {
        __syncthreads();
        const int key0 = kt * 64;
#pragma unroll
        for (int i = 0; i < 16; i++) {
            const int idx = tid + i * 128;
            const int r = idx >> 5, c4 = idx & 31;
            float4 v = *(const float4*)(Kb + (size_t)(key0 + r) * DH_ + c4 * 4);
            v.x = f2tf32(v.x); v.y = f2tf32(v.y);
            v.z = f2tf32(v.z); v.w = f2tf32(v.w);
            *(float4*)(&Ks[r * KPAD + c4 * 4]) = v;
        }
#pragma unroll
        for (int i = 0; i < 16; i++) {
            const int idx = tid + i * 128;
            const int d4 = idx >> 6, key = idx & 63;
            float4 v = *(const float4*)(Vb + (size_t)(key0 + key) * DH_ + d4 * 4);
            Vt[(d4 * 4 + 0) * VPAD + key] = f2tf32(v.x);
            Vt[(d4 * 4 + 1) * VPAD + key] = f2tf32(v.y);
            Vt[(d4 * 4 + 2) * VPAD + key] = f2tf32(v.z);
            Vt[(d4 * 4 + 3) * VPAD + key] = f2tf32(v.w);
        }
        __syncthreads();

        float sacc[8][4];
#pragma unroll
        for (int n = 0; n < 8; n++)
#pragma unroll
            for (int e = 0; e < 4; e++) sacc[n][e] = 0.f;
#pragma unroll
        for (int ks = 0; ks < 16; ks++) {
#pragma unroll
            for (int n = 0; n < 8; n++) {
                uint32_t b[2];
                b[0] = __float_as_uint(Ks[(n * 8 + lr) * KPAD + ks * 8 + lc    ]);
                b[1] = __float_as_uint(Ks[(n * 8 + lr) * KPAD + ks * 8 + lc + 4]);
                mma_tf32(sacc[n], qf[ks], b);
            }
        }

        float mx0 = mr0, mx1 = mr1;
#pragma unroll
        for (int n = 0; n < 8; n++) {
            mx0 = fmaxf(mx0, fmaxf(sacc[n][0], sacc[n][1]));
            mx1 = fmaxf(mx1, fmaxf(sacc[n][2], sacc[n][3]));
        }
        mx0 = fmaxf(mx0, __shfl_xor_sync(0xffffffffu, mx0, 1));
        mx0 = fmaxf(mx0, __shfl_xor_sync(0xffffffffu, mx0, 2));
        mx1 = fmaxf(mx1, __shfl_xor_sync(0xffffffffu, mx1, 1));
        mx1 = fmaxf(mx1, __shfl_xor_sync(0xffffffffu, mx1, 2));
        const float f0 = __expf(mr0 - mx0);
        const float f1 = __expf(mr1 - mx1);
        mr0 = mx0; mr1 = mx1;

        float s0 = 0.f, s1 = 0.f;
#pragma unroll
        for (int n = 0; n < 8; n++) {
            const float p0 = __expf(sacc[n][0] - mx0);
            const float p1 = __expf(sacc[n][1] - mx0);
            const float p2 = __expf(sacc[n][2] - mx1);
            const float p3 = __expf(sacc[n][3] - mx1);
            s0 += p0 + p1; s1 += p2 + p3;
            float2 lo; lo.x = f2tf32(p0); lo.y = f2tf32(p1);
            *(float2*)(&Ps[(qr + lr    ) * PPAD + n * 8 + lc * 2]) = lo;
            float2 hi; hi.x = f2tf32(p2); hi.y = f2tf32(p3);
            *(float2*)(&Ps[(qr + lr + 8) * PPAD + n * 8 + lc * 2]) = hi;
        }
        s0 += __shfl_xor_sync(0xffffffffu, s0, 1);
        s0 += __shfl_xor_sync(0xffffffffu, s0, 2);
        s1 += __shfl_xor_sync(0xffffffffu, s1, 1);
        s1 += __shfl_xor_sync(0xffffffffu, s1, 2);
        lsum0 = lsum0 * f0 + s0;
        lsum1 = lsum1 * f1 + s1;
#pragma unroll
        for (int nt = 0; nt < 16; nt++) {
            oacc[nt][0] *= f0; oacc[nt][1] *= f0;
            oacc[nt][2] *= f1; oacc[nt][3] *= f1;
        }
        __syncwarp();

#pragma unroll
        for (int kk = 0; kk < 8; kk++) {
            uint32_t af[4];
            af[0] = __float_as_uint(Ps[(qr + lr    ) * PPAD + kk * 8 + lc    ]);
            af[1] = __float_as_uint(Ps[(qr + lr + 8) * PPAD + kk * 8 + lc    ]);
            af[2] = __float_as_uint(Ps[(qr + lr    ) * PPAD + kk * 8 + lc + 4]);
            af[3] = __float_as_uint(Ps[(qr + lr + 8) * PPAD + kk * 8 + lc + 4]);
#pragma unroll
            for (int nt = 0; nt < 16; nt++) {
                uint32_t b[2];
                b[0] = __float_as_uint(Vt[(nt * 8 + lr) * VPAD + kk * 8 + lc    ]);
                b[1] = __float_as_uint(Vt[(nt * 8 + lr) * VPAD + kk * 8 + lc + 4]);
                mma_tf32(oacc[nt], af, b);
            }
        }
    }

    const float i0 = 1.f / lsum0, i1 = 1.f / lsum1;
    const int bb = bh >> 4, h = bh & 15;
    const int gr0 = m0 + qr + lr;
    float* o0 = ctx + ((size_t)bb * S_ + gr0) * D_ + h * DH_;
    float* o1 = o0 + (size_t)8 * D_;
#pragma unroll
    for (int nt = 0; nt < 16; nt++) {
        float2 a; a.x = oacc[nt][0] * i0; a.y = oacc[nt][1] * i0;
        *(float2*)(o0 + nt * 8 + lc * 2) = a;
        float2 b; b.x = oacc[nt][2] * i1; b.y = oacc[nt][3] * i1;
        *(float2*)(o1 + nt * 8 + lc * 2) = b;
    }
}

// ---------------------------------------------------------------------------
extern "C" void kernel_launch(void* const* d_in, const int* in_sizes, int n_in,
                              void* d_out, int out_size)
{
    const float* x  = (const float*)d_in[0];
    const float* wq = (const float*)d_in[1];
    const float* bq = (const float*)d_in[2];
    const float* wk = (const float*)d_in[3];
    const float* bk = (const float*)d_in[4];
    const float* wv = (const float*)d_in[5];
    const float* bv = (const float*)d_in[6];
    const float* wo = (const float*)d_in[7];
    const float* bo = (const float*)d_in[8];
    float* out = (float*)d_out;

    float *q, *k, *v, *ctx;
    cudaGetSymbolAddress((void**)&q,   g_q);
    cudaGetSymbolAddress((void**)&k,   g_k);
    cudaGetSymbolAddress((void**)&v,   g_v);
    cudaGetSymbolAddress((void**)&ctx, g_ctx);

    cudaFuncSetAttribute(attn_mma, cudaFuncAttributeMaxDynamicSharedMemorySize, SMEM_ATTN);

    const dim3 ggrid(D_ / 128, M_ / 128);   // (16, 64)

    rope_table_kernel<<<(S_ * 64) / 256, 256>>>();

    gemm_tf32<true><<<ggrid, 128>>>(x, wq, bq, q);
    gemm_tf32<true><<<ggrid, 128>>>(x, wk, bk, k);
    gemm_tf32<true><<<ggrid, 128>>>(x, wv, bv, v);

    const int rope_threads = B_ * H_ * S_ * 64;
    rope_apply2_kernel<<<rope_threads / 256, 256>>>();

    attn_mma<<<dim3(S_ / 64, B_ * H_), 128, SMEM_ATTN>>>(ctx);

    gemm_tf32<false><<<ggrid, 128>>>(ctx, wo, bo, out);
}

// round 11
// speedup vs baseline: 1.6688x; 1.0515x over previous
#include <cuda_runtime.h>
#include <math.h>
#include <stdint.h>

#define B_  4
#define S_  2048
#define D_  2048
#define H_  16
#define DH_ 128
#define M_  (B_*S_)

// Scratch (allowed: __device__ globals)
__device__ float g_q[(size_t)B_*H_*S_*DH_];
__device__ float g_k[(size_t)B_*H_*S_*DH_];
__device__ float g_v[(size_t)B_*H_*S_*DH_];
__device__ float g_ctx[(size_t)B_*S_*D_];
__device__ float g_xr[(size_t)M_*D_];     // tf32-rounded x
__device__ float g_wr[(size_t)D_*D_];     // tf32-rounded weight (reused per GEMM)
__device__ float g_cos[(size_t)S_*64];
__device__ float g_sin[(size_t)S_*64];

// ---------------------------------------------------------------------------
// TF32 helpers
// ---------------------------------------------------------------------------
__device__ __forceinline__ uint32_t tf32u(float x) {
    uint32_t r;
    asm("cvt.rna.tf32.f32 %0, %1;" : "=r"(r) : "f"(x));
    return r;
}
__device__ __forceinline__ float f2tf32(float x) { return __uint_as_float(tf32u(x)); }

__device__ __forceinline__ void mma_tf32(float c[4], const uint32_t a[4], const uint32_t b[2]) {
    asm volatile(
        "mma.sync.aligned.m16n8k8.row.col.f32.tf32.tf32.f32 "
        "{%0,%1,%2,%3}, {%4,%5,%6,%7}, {%8,%9}, {%0,%1,%2,%3};"
        : "+f"(c[0]), "+f"(c[1]), "+f"(c[2]), "+f"(c[3])
        : "r"(a[0]), "r"(a[1]), "r"(a[2]), "r"(a[3]), "r"(b[0]), "r"(b[1]));
}

__device__ __forceinline__ void cp16(uint32_t dst, const void* src) {
    asm volatile("cp.async.cg.shared.global [%0], [%1], 16;" :: "r"(dst), "l"(src));
}

// ---------------------------------------------------------------------------
// Pre-round: out[i] = tf32(in[i]), vectorized
// ---------------------------------------------------------------------------
__global__ __launch_bounds__(256)
void preround_kernel(const float* __restrict__ in, float* __restrict__ out)
{
    const int i = blockIdx.x * blockDim.x + threadIdx.x;
    float4 v = ((const float4*)in)[i];
    v.x = f2tf32(v.x); v.y = f2tf32(v.y);
    v.z = f2tf32(v.z); v.w = f2tf32(v.w);
    ((float4*)out)[i] = v;
}

// ---------------------------------------------------------------------------
// TF32 tensor-core GEMM, cp.async 3-stage: C = A·Wᵀ + bias
// A, W must be PRE-ROUNDED to tf32. 128x128 block, 4 warps, 64x64 warp tile.
// ---------------------------------------------------------------------------
#define STG 3

template<bool HEADS>
__global__ __launch_bounds__(128)
void gemm_tf32(const float* __restrict__ A, const float* __restrict__ W,
               const float* __restrict__ bias, float* __restrict__ C)
{
    __shared__ float As[STG][128][20];
    __shared__ float Ws[STG][128][20];
    const int K  = D_;
    const int m0 = blockIdx.y * 128;
    const int n0 = blockIdx.x * 128;
    const int tid  = threadIdx.x;
    const int warp = tid >> 5, lane = tid & 31;
    const int wy = warp >> 1, wx = warp & 1;
    const int lr = lane >> 2, lc = lane & 3;

    // per-thread load coords: row r (0..127), chunk c4 (0..3)
    const int r_  = tid >> 2;
    const int c4_ = tid & 3;
    const float* Ag = A + (size_t)(m0 + r_) * K + c4_ * 4;          // +u*32 rows via tid
    const float* Wg = W + (size_t)(n0 + r_) * K + c4_ * 4;

    float acc[4][8][4];
#pragma unroll
    for (int ti = 0; ti < 4; ti++)
#pragma unroll
        for (int nt = 0; nt < 8; nt++)
#pragma unroll
            for (int e = 0; e < 4; e++) acc[ti][nt][e] = 0.f;

    auto issue = [&](int st, int k0) {
#pragma unroll
        for (int u = 0; u < 4; u++) {
            const int f = tid + u * 128;
            const int r = f >> 2, c4 = f & 3;
            cp16((uint32_t)__cvta_generic_to_shared(&As[st][r][c4 * 4]),
                 A + (size_t)(m0 + r) * K + k0 + c4 * 4);
            cp16((uint32_t)__cvta_generic_to_shared(&Ws[st][r][c4 * 4]),
                 W + (size_t)(n0 + r) * K + k0 + c4 * 4);
        }
        asm volatile("cp.async.commit_group;");
    };

    issue(0, 0);
    issue(1, 16);

    const int NIT = K / 16;                     // 128
#pragma unroll 1
    for (int it = 0; it < NIT; it++) {
        asm volatile("cp.async.wait_group %0;" :: "n"(STG - 2));
        __syncthreads();
        if (it + STG - 1 < NIT) {
            issue((it + STG - 1) % STG, (it + STG - 1) * 16);
        } else {
            asm volatile("cp.async.commit_group;");  // keep group count invariant
        }
        const int cur = it % STG;

#pragma unroll
        for (int kk = 0; kk < 16; kk += 8) {
            uint32_t afr[4][4], bfr[8][2];
            const int ac = kk + lc;
#pragma unroll
            for (int ti = 0; ti < 4; ti++) {
                const int ar = wy * 64 + ti * 16 + lr;
                afr[ti][0] = __float_as_uint(As[cur][ar    ][ac]);
                afr[ti][1] = __float_as_uint(As[cur][ar + 8][ac]);
                afr[ti][2] = __float_as_uint(As[cur][ar    ][ac + 4]);
                afr[ti][3] = __float_as_uint(As[cur][ar + 8][ac + 4]);
            }
#pragma unroll
            for (int nt = 0; nt < 8; nt++) {
                const int br = wx * 64 + nt * 8 + lr;
                bfr[nt][0] = __float_as_uint(Ws[cur][br][ac]);
                bfr[nt][1] = __float_as_uint(Ws[cur][br][ac + 4]);
            }
#pragma unroll
            for (int ti = 0; ti < 4; ti++)
#pragma unroll
                for (int nt = 0; nt < 8; nt++)
                    mma_tf32(acc[ti][nt], afr[ti], bfr[nt]);
        }
    }

#pragma unroll
    for (int ti = 0; ti < 4; ti++) {
#pragma unroll
        for (int nt = 0; nt < 8; nt++) {
            const int row = m0 + wy * 64 + ti * 16 + lr;
            const int col = n0 + wx * 64 + nt * 8 + lc * 2;
#pragma unroll
            for (int e = 0; e < 4; e++) {
                const int m = row + (e >> 1) * 8;
                const int n = col + (e & 1);
                const float v = acc[ti][nt][e] + bias[n];
                if (HEADS) {
                    const int bb = m >> 11, s = m & (S_ - 1);
                    const int h = n >> 7, dh = n & 127;
                    C[(((size_t)bb * H_ + h) * S_ + s) * DH_ + dh] = v;
                } else {
                    C[(size_t)m * D_ + n] = v;
                }
            }
        }
    }
}

// ---------------------------------------------------------------------------
// RoPE cos/sin table
// ---------------------------------------------------------------------------
__global__ __launch_bounds__(256)
void rope_table_kernel()
{
    const int idx = blockIdx.x * blockDim.x + threadIdx.x;
    const int p = idx & 63;
    const int s = idx >> 6;
    const float invf = (float)exp(-(double)p * (log(10000.0) / 64.0));
    const float ang  = (float)s * invf;
    g_cos[idx] = (float)cos((double)ang);
    g_sin[idx] = (float)sin((double)ang);
}

// ---------------------------------------------------------------------------
// TF32 flash attention with FUSED RoPE on Q/K loads (reads unroped g_q/g_k).
// 64 q-rows/CTA, 4 warps, Q register-resident, 88KB smem -> 2 CTAs/SM.
// ---------------------------------------------------------------------------
#define KPAD 132
#define VPAD 68
#define PPAD 76
#define SMEM_ATTN ((64*KPAD + 128*VPAD + 64*PPAD) * 4)

__global__ __launch_bounds__(128)
void attn_mma(float* __restrict__ ctx)
{
    extern __shared__ float sm[];
    float* Ks = sm;
    float* Vt = sm + 64 * KPAD;
    float* Ps = sm + 64 * KPAD + 128 * VPAD;

    const int bh  = blockIdx.y;
    const int m0  = blockIdx.x * 64;
    const int tid = threadIdx.x;
    const int warp = tid >> 5, lane = tid & 31;
    const int lr = lane >> 2, lc = lane & 3;
    const int qr = warp * 16;

    const float* Qb = g_q + (size_t)bh * S_ * DH_;
    const float* Kb = g_k + (size_t)bh * S_ * DH_;
    const float* Vb = g_v + (size_t)bh * S_ * DH_;

    const float scale = 0.08838834764831845f;   // 1/sqrt(128)

    // ---- stage Q with fused rope (pairs p, p+64), scaled, tf32 ----
#pragma unroll
    for (int i = 0; i < 8; i++) {
        const int idx = tid + i * 128;      // 64 rows x 16 pair-chunks
        const int r  = idx >> 4;
        const int p4 = idx & 15;
        const int s  = m0 + r;
        const float4 v1 = *(const float4*)(Qb + (size_t)s * DH_ + p4 * 4);
        const float4 v2 = *(const float4*)(Qb + (size_t)s * DH_ + p4 * 4 + 64);
        const float4 cs = *(const float4*)(g_cos + s * 64 + p4 * 4);
        const float4 sn = *(const float4*)(g_sin + s * 64 + p4 * 4);
        float4 o1, o2;
        o1.x = f2tf32((v1.x * cs.x - v2.x * sn.x) * scale);
        o1.y = f2tf32((v1.y * cs.y - v2.y * sn.y) * scale);
        o1.z = f2tf32((v1.z * cs.z - v2.z * sn.z) * scale);
        o1.w = f2tf32((v1.w * cs.w - v2.w * sn.w) * scale);
        o2.x = f2tf32((v2.x * cs.x + v1.x * sn.x) * scale);
        o2.y = f2tf32((v2.y * cs.y + v1.y * sn.y) * scale);
        o2.z = f2tf32((v2.z * cs.z + v1.z * sn.z) * scale);
        o2.w = f2tf32((v2.w * cs.w + v1.w * sn.w) * scale);
        *(float4*)(&Ks[r * KPAD + p4 * 4])      = o1;
        *(float4*)(&Ks[r * KPAD + p4 * 4 + 64]) = o2;
    }
    __syncthreads();
    uint32_t qf[16][4];
#pragma unroll
    for (int ks = 0; ks < 16; ks++) {
        qf[ks][0] = __float_as_uint(Ks[(qr + lr    ) * KPAD + ks * 8 + lc    ]);
        qf[ks][1] = __float_as_uint(Ks[(qr + lr + 8) * KPAD + ks * 8 + lc    ]);
        qf[ks][2] = __float_as_uint(Ks[(qr + lr    ) * KPAD + ks * 8 + lc + 4]);
        qf[ks][3] = __float_as_uint(Ks[(qr + lr + 8) * KPAD + ks * 8 + lc + 4]);
    }

    float oacc[16][4];
#pragma unroll
    for (int nt = 0; nt < 16; nt++)
#pragma unroll
        for (int e = 0; e < 4; e++) oacc[nt][e] = 0.f;
    float mr0 = -1e30f, mr1 = -1e30f, lsum0 = 0.f, lsum1 = 0.f;

    for (int kt = 0; kt < 32; kt++) {
        __syncthreads();
        const int key0 = kt * 64;
        // ---- K tile with fused rope ----
#pragma unroll
        for (int i = 0; i < 8; i++) {
            const int idx = tid + i * 128;
            const int r  = idx >> 4;
            const int p4 = idx & 15;
            const int s  = key0 + r;
            const float4 v1 = *(const float4*)(Kb + (size_t)s * DH_ + p4 * 4);
            const float4 v2 = *(const float4*)(Kb + (size_t)s * DH_ + p4 * 4 + 64);
            const float4 cs = *(const float4*)(g_cos + s * 64 + p4 * 4);
            const float4 sn = *(const float4*)(g_sin + s * 64 + p4 * 4);
            float4 o1, o2;
            o1.x = f2tf32(v1.x * cs.x - v2.x * sn.x);
            o1.y = f2tf32(v1.y * cs.y - v2.y * sn.y);
            o1.z = f2tf32(v1.z * cs.z - v2.z * sn.z);
            o1.w = f2tf32(v1.w * cs.w - v2.w * sn.w);
            o2.x = f2tf32(v2.x * cs.x + v1.x * sn.x);
            o2.y = f2tf32(v2.y * cs.y + v1.y * sn.y);
            o2.z = f2tf32(v2.z * cs.z + v1.z * sn.z);
            o2.w = f2tf32(v2.w * cs.w + v1.w * sn.w);
            *(float4*)(&Ks[r * KPAD + p4 * 4])      = o1;
            *(float4*)(&Ks[r * KPAD + p4 * 4 + 64]) = o2;
        }
        // ---- V tile transposed ----
#pragma unroll
        for (int i = 0; i < 16; i++) {
            const int idx = tid + i * 128;
            const int d4 = idx >> 6, key = idx & 63;
            float4 v = *(const float4*)(Vb + (size_t)(key0 + key) * DH_ + d4 * 4);
            Vt[(d4 * 4 + 0) * VPAD + key] = f2tf32(v.x);
            Vt[(d4 * 4 + 1) * VPAD + key] = f2tf32(v.y);
            Vt[(d4 * 4 + 2) * VPAD + key] = f2tf32(v.z);
            Vt[(d4 * 4 + 3) * VPAD + key] = f2tf32(v.w);
        }
        __syncthreads();

        float sacc[8][4];
#pragma unroll
        for (int n = 0; n < 8; n++)
#pragma unroll
            for (int e = 0; e < 4; e++) sacc[n][e] = 0.f;
#pragma unroll
        for (int ks = 0; ks < 16; ks++) {
#pragma unroll
            for (int n = 0; n < 8; n++) {
                uint32_t b[2];
                b[0] = __float_as_uint(Ks[(n * 8 + lr) * KPAD + ks * 8 + lc    ]);
                b[1] = __float_as_uint(Ks[(n * 8 + lr) * KPAD + ks * 8 + lc + 4]);
                mma_tf32(sacc[n], qf[ks], b);
            }
        }

        float mx0 = mr0, mx1 = mr1;
#pragma unroll
        for (int n = 0; n < 8; n++) {
            mx0 = fmaxf(mx0, fmaxf(sacc[n][0], sacc[n][1]));
            mx1 = fmaxf(mx1, fmaxf(sacc[n][2], sacc[n][3]));
        }
        mx0 = fmaxf(mx0, __shfl_xor_sync(0xffffffffu, mx0, 1));
        mx0 = fmaxf(mx0, __shfl_xor_sync(0xffffffffu, mx0, 2));
        mx1 = fmaxf(mx1, __shfl_xor_sync(0xffffffffu, mx1, 1));
        mx1 = fmaxf(mx1, __shfl_xor_sync(0xffffffffu, mx1, 2));
        const float f0 = __expf(mr0 - mx0);
        const float f1 = __expf(mr1 - mx1);
        mr0 = mx0; mr1 = mx1;

        float s0 = 0.f, s1 = 0.f;
#pragma unroll
        for (int n = 0; n < 8; n++) {
            const float p0 = __expf(sacc[n][0] - mx0);
            const float p1 = __expf(sacc[n][1] - mx0);
            const float p2 = __expf(sacc[n][2] - mx1);
            const float p3 = __expf(sacc[n][3] - mx1);
            s0 += p0 + p1; s1 += p2 + p3;
            float2 lo; lo.x = f2tf32(p0); lo.y = f2tf32(p1);
            *(float2*)(&Ps[(qr + lr    ) * PPAD + n * 8 + lc * 2]) = lo;
            float2 hi; hi.x = f2tf32(p2); hi.y = f2tf32(p3);
            *(float2*)(&Ps[(qr + lr + 8) * PPAD + n * 8 + lc * 2]) = hi;
        }
        s0 += __shfl_xor_sync(0xffffffffu, s0, 1);
        s0 += __shfl_xor_sync(0xffffffffu, s0, 2);
        s1 += __shfl_xor_sync(0xffffffffu, s1, 1);
        s1 += __shfl_xor_sync(0xffffffffu, s1, 2);
        lsum0 = lsum0 * f0 + s0;
        lsum1 = lsum1 * f1 + s1;
#pragma unroll
        for (int nt = 0; nt < 16; nt++) {
            oacc[nt][0] *= f0; oacc[nt][1] *= f0;
            oacc[nt][2] *= f1; oacc[nt][3] *= f1;
        }
        __syncwarp();

#pragma unroll
        for (int kk = 0; kk < 8; kk++) {
            uint32_t af[4];
            af[0] = __float_as_uint(Ps[(qr + lr    ) * PPAD + kk * 8 + lc    ]);
            af[1] = __float_as_uint(Ps[(qr + lr + 8) * PPAD + kk * 8 + lc    ]);
            af[2] = __float_as_uint(Ps[(qr + lr    ) * PPAD + kk * 8 + lc + 4]);
            af[3] = __float_as_uint(Ps[(qr + lr + 8) * PPAD + kk * 8 + lc + 4]);
#pragma unroll
            for (int nt = 0; nt < 16; nt++) {
                uint32_t b[2];
                b[0] = __float_as_uint(Vt[(nt * 8 + lr) * VPAD + kk * 8 + lc    ]);
                b[1] = __float_as_uint(Vt[(nt * 8 + lr) * VPAD + kk * 8 + lc + 4]);
                mma_tf32(oacc[nt], af, b);
            }
        }
    }

    // epilogue: normalize, pre-round to tf32 (final GEMM consumes directly)
    const float i0 = 1.f / lsum0, i1 = 1.f / lsum1;
    const int bb = bh >> 4, h = bh & 15;
    const int gr0 = m0 + qr + lr;
    float* o0 = ctx + ((size_t)bb * S_ + gr0) * D_ + h * DH_;
    float* o1 = o0 + (size_t)8 * D_;
#pragma unroll
    for (int nt = 0; nt < 16; nt++) {
        float2 a; a.x = f2tf32(oacc[nt][0] * i0); a.y = f2tf32(oacc[nt][1] * i0);
        *(float2*)(o0 + nt * 8 + lc * 2) = a;
        float2 b; b.x = f2tf32(oacc[nt][2] * i1); b.y = f2tf32(oacc[nt][3] * i1);
        *(float2*)(o1 + nt * 8 + lc * 2) = b;
    }
}

// ---------------------------------------------------------------------------
extern "C" void kernel_launch(void* const* d_in, const int* in_sizes, int n_in,
                              void* d_out, int out_size)
{
    const float* x  = (const float*)d_in[0];
    const float* wq = (const float*)d_in[1];
    const float* bq = (const float*)d_in[2];
    const float* wk = (const float*)d_in[3];
    const float* bk = (const float*)d_in[4];
    const float* wv = (const float*)d_in[5];
    const float* bv = (const float*)d_in[6];
    const float* wo = (const float*)d_in[7];
    const float* bo = (const float*)d_in[8];
    float* out = (float*)d_out;

    float *q, *k, *v, *ctx, *xr, *wr;
    cudaGetSymbolAddress((void**)&q,   g_q);
    cudaGetSymbolAddress((void**)&k,   g_k);
    cudaGetSymbolAddress((void**)&v,   g_v);
    cudaGetSymbolAddress((void**)&ctx, g_ctx);
    cudaGetSymbolAddress((void**)&xr,  g_xr);
    cudaGetSymbolAddress((void**)&wr,  g_wr);

    cudaFuncSetAttribute(attn_mma, cudaFuncAttributeMaxDynamicSharedMemorySize, SMEM_ATTN);

    const dim3 ggrid(D_ / 128, M_ / 128);        // (16, 64)
    const int XB = (M_ * D_) / 4 / 256;          // preround blocks for x
    const int WB = (D_ * D_) / 4 / 256;          // preround blocks for weights

    rope_table_kernel<<<(S_ * 64) / 256, 256>>>();
    preround_kernel<<<XB, 256>>>(x, xr);

    preround_kernel<<<WB, 256>>>(wq, wr);
    gemm_tf32<true><<<ggrid, 128>>>(xr, wr, bq, q);
    preround_kernel<<<WB, 256>>>(wk, wr);
    gemm_tf32<true><<<ggrid, 128>>>(xr, wr, bk, k);
    preround_kernel<<<WB, 256>>>(wv, wr);
    gemm_tf32<true><<<ggrid, 128>>>(xr, wr, bv, v);

    attn_mma<<<dim3(S_ / 64, B_ * H_), 128, SMEM_ATTN>>>(ctx);

    preround_kernel<<<WB, 256>>>(wo, wr);
    gemm_tf32<false><<<ggrid, 128>>>(ctx, wr, bo, out);
}

// round 12
// speedup vs baseline: 2.0508x; 1.2289x over previous
#include <cuda_runtime.h>
#include <math.h>
#include <stdint.h>

#define B_  4
#define S_  2048
#define D_  2048
#define H_  16
#define DH_ 128
#define M_  (B_*S_)

// Scratch (allowed: __device__ globals)
__device__ float g_q[(size_t)B_*H_*S_*DH_];    // Q [bh][s][dh]  (unroped)
__device__ float g_k[(size_t)B_*H_*S_*DH_];    // K [bh][s][dh]  (unroped)
__device__ float g_v[(size_t)B_*H_*S_*DH_];    // V [bh][dh][s]  (TRANSPOSED, tf32)
__device__ float g_ctx[(size_t)B_*S_*D_];
__device__ float g_xr[(size_t)M_*D_];          // tf32 x; later reused as roped-K
__device__ float g_wr[(size_t)D_*D_];          // tf32 weight (reused per GEMM)
__device__ float g_cos[(size_t)S_*64];
__device__ float g_sin[(size_t)S_*64];

// ---------------------------------------------------------------------------
// Helpers
// ---------------------------------------------------------------------------
__device__ __forceinline__ uint32_t tf32u(float x) {
    uint32_t r;
    asm("cvt.rna.tf32.f32 %0, %1;" : "=r"(r) : "f"(x));
    return r;
}
__device__ __forceinline__ float f2tf32(float x) { return __uint_as_float(tf32u(x)); }

__device__ __forceinline__ void mma_tf32(float c[4], const uint32_t a[4], const uint32_t b[2]) {
    asm volatile(
        "mma.sync.aligned.m16n8k8.row.col.f32.tf32.tf32.f32 "
        "{%0,%1,%2,%3}, {%4,%5,%6,%7}, {%8,%9}, {%0,%1,%2,%3};"
        : "+f"(c[0]), "+f"(c[1]), "+f"(c[2]), "+f"(c[3])
        : "r"(a[0]), "r"(a[1]), "r"(a[2]), "r"(a[3]), "r"(b[0]), "r"(b[1]));
}

__device__ __forceinline__ void cp16(uint32_t dst, const void* src) {
    asm volatile("cp.async.cg.shared.global [%0], [%1], 16;" :: "r"(dst), "l"(src));
}

// ---------------------------------------------------------------------------
// Pre-round: out[i] = tf32(in[i])
// ---------------------------------------------------------------------------
__global__ __launch_bounds__(256)
void preround_kernel(const float* __restrict__ in, float* __restrict__ out)
{
    const int i = blockIdx.x * blockDim.x + threadIdx.x;
    float4 v = ((const float4*)in)[i];
    v.x = f2tf32(v.x); v.y = f2tf32(v.y);
    v.z = f2tf32(v.z); v.w = f2tf32(v.w);
    ((float4*)out)[i] = v;
}

// ---------------------------------------------------------------------------
// TF32 GEMM, cp.async 3-stage (R10-proven). OUT: 0=flat, 1=heads, 2=heads
// transposed [bh][dh][s] + tf32-rounded (for V).
// ---------------------------------------------------------------------------
#define STG 3

template<int OUT>
__global__ __launch_bounds__(128)
void gemm_tf32(const float* __restrict__ A, const float* __restrict__ W,
               const float* __restrict__ bias, float* __restrict__ C)
{
    __shared__ float As[STG][128][20];
    __shared__ float Ws[STG][128][20];
    const int K  = D_;
    const int m0 = blockIdx.y * 128;
    const int n0 = blockIdx.x * 128;
    const int tid  = threadIdx.x;
    const int warp = tid >> 5, lane = tid & 31;
    const int wy = warp >> 1, wx = warp & 1;
    const int lr = lane >> 2, lc = lane & 3;

    float acc[4][8][4];
#pragma unroll
    for (int ti = 0; ti < 4; ti++)
#pragma unroll
        for (int nt = 0; nt < 8; nt++)
#pragma unroll
            for (int e = 0; e < 4; e++) acc[ti][nt][e] = 0.f;

    auto issue = [&](int st, int k0) {
#pragma unroll
        for (int u = 0; u < 4; u++) {
            const int f = tid + u * 128;
            const int r = f >> 2, c4 = f & 3;
            cp16((uint32_t)__cvta_generic_to_shared(&As[st][r][c4 * 4]),
                 A + (size_t)(m0 + r) * K + k0 + c4 * 4);
            cp16((uint32_t)__cvta_generic_to_shared(&Ws[st][r][c4 * 4]),
                 W + (size_t)(n0 + r) * K + k0 + c4 * 4);
        }
        asm volatile("cp.async.commit_group;");
    };

    issue(0, 0);
    issue(1, 16);

    const int NIT = K / 16;
#pragma unroll 1
    for (int it = 0; it < NIT; it++) {
        asm volatile("cp.async.wait_group %0;" :: "n"(STG - 2));
        __syncthreads();
        if (it + STG - 1 < NIT) {
            issue((it + STG - 1) % STG, (it + STG - 1) * 16);
        } else {
            asm volatile("cp.async.commit_group;");
        }
        const int cur = it % STG;

#pragma unroll
        for (int kk = 0; kk < 16; kk += 8) {
            uint32_t afr[4][4], bfr[8][2];
            const int ac = kk + lc;
#pragma unroll
            for (int ti = 0; ti < 4; ti++) {
                const int ar = wy * 64 + ti * 16 + lr;
                afr[ti][0] = __float_as_uint(As[cur][ar    ][ac]);
                afr[ti][1] = __float_as_uint(As[cur][ar + 8][ac]);
                afr[ti][2] = __float_as_uint(As[cur][ar    ][ac + 4]);
                afr[ti][3] = __float_as_uint(As[cur][ar + 8][ac + 4]);
            }
#pragma unroll
            for (int nt = 0; nt < 8; nt++) {
                const int br = wx * 64 + nt * 8 + lr;
                bfr[nt][0] = __float_as_uint(Ws[cur][br][ac]);
                bfr[nt][1] = __float_as_uint(Ws[cur][br][ac + 4]);
            }
#pragma unroll
            for (int ti = 0; ti < 4; ti++)
#pragma unroll
                for (int nt = 0; nt < 8; nt++)
                    mma_tf32(acc[ti][nt], afr[ti], bfr[nt]);
        }
    }

#pragma unroll
    for (int ti = 0; ti < 4; ti++) {
#pragma unroll
        for (int nt = 0; nt < 8; nt++) {
            const int row = m0 + wy * 64 + ti * 16 + lr;
            const int col = n0 + wx * 64 + nt * 8 + lc * 2;
#pragma unroll
            for (int e = 0; e < 4; e++) {
                const int m = row + (e >> 1) * 8;
                const int n = col + (e & 1);
                const float v = acc[ti][nt][e] + bias[n];
                if (OUT == 1) {
                    const int bb = m >> 11, s = m & (S_ - 1);
                    const int h = n >> 7, dh = n & 127;
                    C[(((size_t)bb * H_ + h) * S_ + s) * DH_ + dh] = v;
                } else if (OUT == 2) {
                    const int bb = m >> 11, s = m & (S_ - 1);
                    const int h = n >> 7, dh = n & 127;
                    C[(((size_t)(bb * H_ + h)) * DH_ + dh) * S_ + s] = f2tf32(v);
                } else {
                    C[(size_t)m * D_ + n] = v;
                }
            }
        }
    }
}

// ---------------------------------------------------------------------------
// RoPE table + K pre-rope (roped, tf32, into g_xr)
// ---------------------------------------------------------------------------
__global__ __launch_bounds__(256)
void rope_table_kernel()
{
    const int idx = blockIdx.x * blockDim.x + threadIdx.x;
    const int p = idx & 63;
    const int s = idx >> 6;
    const float invf = (float)exp(-(double)p * (log(10000.0) / 64.0));
    const float ang  = (float)s * invf;
    g_cos[idx] = (float)cos((double)ang);
    g_sin[idx] = (float)sin((double)ang);
}

__global__ __launch_bounds__(256)
void rope_k_kernel()
{
    const int idx = blockIdx.x * blockDim.x + threadIdx.x;  // B*H*S*64
    const int p   = idx & 63;
    const int row = idx >> 6;
    const int s   = row & (S_ - 1);
    const float cs = g_cos[s * 64 + p];
    const float sn = g_sin[s * 64 + p];
    const float* kb = g_k + (size_t)row * DH_;
    float* kr = g_xr + (size_t)row * DH_;
    const float k1 = kb[p], k2 = kb[p + 64];
    kr[p]      = f2tf32(k1 * cs - k2 * sn);
    kr[p + 64] = f2tf32(k2 * cs + k1 * sn);
}

// ---------------------------------------------------------------------------
// TF32 flash attention v3: 256 threads / 8 warps, 128 q-rows per CTA
// (16 rows per warp, identical per-warp math to R3), 64-key KV tiles
// DOUBLE-BUFFERED via cp.async from pre-roped K (g_xr) and transposed V (g_v).
// ---------------------------------------------------------------------------
#define KPAD 132
#define VPAD 68
#define PPAD 76
// smem: KB [2][64][KPAD] (Q staging uses the contiguous 128 rows), VB [2][128][VPAD], Ps [128][PPAD]
#define SMEM_ATTN ((128*KPAD + 2*128*VPAD + 128*PPAD) * 4)

__global__ __launch_bounds__(256)
void attn_mma(float* __restrict__ ctx)
{
    extern __shared__ float sm[];
    float* KB = sm;                        // 128*KPAD floats (2 x 64-row buffers)
    float* VB = sm + 128 * KPAD;           // 2 x 128*VPAD
    float* Ps = VB + 2 * 128 * VPAD;       // 128*PPAD

    const int bh  = blockIdx.y;
    const int m0  = blockIdx.x * 128;
    const int tid = threadIdx.x;
    const int warp = tid >> 5, lane = tid & 31;
    const int lr = lane >> 2, lc = lane & 3;
    const int qr = warp * 16;

    const float* Qb = g_q  + (size_t)bh * S_ * DH_;
    const float* Kr = g_xr + (size_t)bh * S_ * DH_;       // roped, tf32
    const float* Vt = g_v  + (size_t)bh * DH_ * S_;       // [dh][s], tf32

    const float scale = 0.08838834764831845f;   // 1/sqrt(128)

    // ---- stage Q with fused rope (pairs p,p+64), scaled, tf32, into KB ----
#pragma unroll
    for (int i = 0; i < 8; i++) {
        const int idx = tid + i * 256;      // 128 rows x 16 pair-chunks
        const int r  = idx >> 4;
        const int p4 = idx & 15;
        const int s  = m0 + r;
        const float4 v1 = *(const float4*)(Qb + (size_t)s * DH_ + p4 * 4);
        const float4 v2 = *(const float4*)(Qb + (size_t)s * DH_ + p4 * 4 + 64);
        const float4 cs = *(const float4*)(g_cos + s * 64 + p4 * 4);
        const float4 sn = *(const float4*)(g_sin + s * 64 + p4 * 4);
        float4 o1, o2;
        o1.x = f2tf32((v1.x * cs.x - v2.x * sn.x) * scale);
        o1.y = f2tf32((v1.y * cs.y - v2.y * sn.y) * scale);
        o1.z = f2tf32((v1.z * cs.z - v2.z * sn.z) * scale);
        o1.w = f2tf32((v1.w * cs.w - v2.w * sn.w) * scale);
        o2.x = f2tf32((v2.x * cs.x + v1.x * sn.x) * scale);
        o2.y = f2tf32((v2.y * cs.y + v1.y * sn.y) * scale);
        o2.z = f2tf32((v2.z * cs.z + v1.z * sn.z) * scale);
        o2.w = f2tf32((v2.w * cs.w + v1.w * sn.w) * scale);
        *(float4*)(&KB[r * KPAD + p4 * 4])      = o1;
        *(float4*)(&KB[r * KPAD + p4 * 4 + 64]) = o2;
    }
    __syncthreads();
    uint32_t qf[16][4];
#pragma unroll
    for (int ks = 0; ks < 16; ks++) {
        qf[ks][0] = __float_as_uint(KB[(qr + lr    ) * KPAD + ks * 8 + lc    ]);
        qf[ks][1] = __float_as_uint(KB[(qr + lr + 8) * KPAD + ks * 8 + lc    ]);
        qf[ks][2] = __float_as_uint(KB[(qr + lr    ) * KPAD + ks * 8 + lc + 4]);
        qf[ks][3] = __float_as_uint(KB[(qr + lr + 8) * KPAD + ks * 8 + lc + 4]);
    }
    __syncthreads();   // Q fully consumed before K tiles overwrite KB

    // ---- cp.async tile issue: K 64x128 (32KB) + V 128x64 (32KB) per tile ----
    auto issue_tile = [&](int t) {
        const int buf = t & 1;
        const int key0 = t * 64;
        float* kb = KB + buf * 64 * KPAD;
        float* vb = VB + buf * 128 * VPAD;
#pragma unroll
        for (int u = 0; u < 8; u++) {
            const int c = tid + u * 256;            // 2048 chunks
            const int r = c >> 5, c4 = c & 31;
            cp16((uint32_t)__cvta_generic_to_shared(&kb[r * KPAD + c4 * 4]),
                 Kr + (size_t)(key0 + r) * DH_ + c4 * 4);
        }
#pragma unroll
        for (int u = 0; u < 8; u++) {
            const int c = tid + u * 256;            // 2048 chunks
            const int r = c >> 4, c4 = c & 15;
            cp16((uint32_t)__cvta_generic_to_shared(&vb[r * VPAD + c4 * 4]),
                 Vt + (size_t)r * S_ + key0 + c4 * 4);
        }
        asm volatile("cp.async.commit_group;");
    };

    issue_tile(0);
    issue_tile(1);

    float oacc[16][4];
#pragma unroll
    for (int nt = 0; nt < 16; nt++)
#pragma unroll
        for (int e = 0; e < 4; e++) oacc[nt][e] = 0.f;
    float mr0 = -1e30f, mr1 = -1e30f, lsum0 = 0.f, lsum1 = 0.f;

#pragma unroll 1
    for (int kt = 0; kt < 32; kt++) {
        asm volatile("cp.async.wait_group %0;" :: "n"(1));
        __syncthreads();
        const int buf = kt & 1;
        const float* kb = KB + buf * 64 * KPAD;
        const float* vb = VB + buf * 128 * VPAD;

        // ---- S = Q·Kᵀ ----
        float sacc[8][4];
#pragma unroll
        for (int n = 0; n < 8; n++)
#pragma unroll
            for (int e = 0; e < 4; e++) sacc[n][e] = 0.f;
#pragma unroll
        for (int ks = 0; ks < 16; ks++) {
#pragma unroll
            for (int n = 0; n < 8; n++) {
                uint32_t b[2];
                b[0] = __float_as_uint(kb[(n * 8 + lr) * KPAD + ks * 8 + lc    ]);
                b[1] = __float_as_uint(kb[(n * 8 + lr) * KPAD + ks * 8 + lc + 4]);
                mma_tf32(sacc[n], qf[ks], b);
            }
        }

        // ---- online softmax ----
        float mx0 = mr0, mx1 = mr1;
#pragma unroll
        for (int n = 0; n < 8; n++) {
            mx0 = fmaxf(mx0, fmaxf(sacc[n][0], sacc[n][1]));
            mx1 = fmaxf(mx1, fmaxf(sacc[n][2], sacc[n][3]));
        }
        mx0 = fmaxf(mx0, __shfl_xor_sync(0xffffffffu, mx0, 1));
        mx0 = fmaxf(mx0, __shfl_xor_sync(0xffffffffu, mx0, 2));
        mx1 = fmaxf(mx1, __shfl_xor_sync(0xffffffffu, mx1, 1));
        mx1 = fmaxf(mx1, __shfl_xor_sync(0xffffffffu, mx1, 2));
        const float f0 = __expf(mr0 - mx0);
        const float f1 = __expf(mr1 - mx1);
        mr0 = mx0; mr1 = mx1;

        float s0 = 0.f, s1 = 0.f;
#pragma unroll
        for (int n = 0; n < 8; n++) {
            const float p0 = __expf(sacc[n][0] - mx0);
            const float p1 = __expf(sacc[n][1] - mx0);
            const float p2 = __expf(sacc[n][2] - mx1);
            const float p3 = __expf(sacc[n][3] - mx1);
            s0 += p0 + p1; s1 += p2 + p3;
            float2 lo; lo.x = f2tf32(p0); lo.y = f2tf32(p1);
            *(float2*)(&Ps[(qr + lr    ) * PPAD + n * 8 + lc * 2]) = lo;
            float2 hi; hi.x = f2tf32(p2); hi.y = f2tf32(p3);
            *(float2*)(&Ps[(qr + lr + 8) * PPAD + n * 8 + lc * 2]) = hi;
        }
        s0 += __shfl_xor_sync(0xffffffffu, s0, 1);
        s0 += __shfl_xor_sync(0xffffffffu, s0, 2);
        s1 += __shfl_xor_sync(0xffffffffu, s1, 1);
        s1 += __shfl_xor_sync(0xffffffffu, s1, 2);
        lsum0 = lsum0 * f0 + s0;
        lsum1 = lsum1 * f1 + s1;
#pragma unroll
        for (int nt = 0; nt < 16; nt++) {
            oacc[nt][0] *= f0; oacc[nt][1] *= f0;
            oacc[nt][2] *= f1; oacc[nt][3] *= f1;
        }
        __syncwarp();  // own-warp P stores before P fragment loads

        // ---- O += P·V ----
#pragma unroll
        for (int kk = 0; kk < 8; kk++) {
            uint32_t af[4];
            af[0] = __float_as_uint(Ps[(qr + lr    ) * PPAD + kk * 8 + lc    ]);
            af[1] = __float_as_uint(Ps[(qr + lr + 8) * PPAD + kk * 8 + lc    ]);
            af[2] = __float_as_uint(Ps[(qr + lr    ) * PPAD + kk * 8 + lc + 4]);
            af[3] = __float_as_uint(Ps[(qr + lr + 8) * PPAD + kk * 8 + lc + 4]);
#pragma unroll
            for (int nt = 0; nt < 16; nt++) {
                uint32_t b[2];
                b[0] = __float_as_uint(vb[(nt * 8 + lr) * VPAD + kk * 8 + lc    ]);
                b[1] = __float_as_uint(vb[(nt * 8 + lr) * VPAD + kk * 8 + lc + 4]);
                mma_tf32(oacc[nt], af, b);
            }
        }

        __syncthreads();  // all warps done with buf before overwrite
        if (kt + 2 < 32) {
            issue_tile(kt + 2);
        } else {
            asm volatile("cp.async.commit_group;");
        }
    }

    // ---- epilogue: normalize, tf32-round (final GEMM consumes directly) ----
    const float i0 = 1.f / lsum0, i1 = 1.f / lsum1;
    const int bb = bh >> 4, h = bh & 15;
    const int gr0 = m0 + qr + lr;
    float* o0 = ctx + ((size_t)bb * S_ + gr0) * D_ + h * DH_;
    float* o1 = o0 + (size_t)8 * D_;
#pragma unroll
    for (int nt = 0; nt < 16; nt++) {
        float2 a; a.x = f2tf32(oacc[nt][0] * i0); a.y = f2tf32(oacc[nt][1] * i0);
        *(float2*)(o0 + nt * 8 + lc * 2) = a;
        float2 b; b.x = f2tf32(oacc[nt][2] * i1); b.y = f2tf32(oacc[nt][3] * i1);
        *(float2*)(o1 + nt * 8 + lc * 2) = b;
    }
}

// ---------------------------------------------------------------------------
extern "C" void kernel_launch(void* const* d_in, const int* in_sizes, int n_in,
                              void* d_out, int out_size)
{
    const float* x  = (const float*)d_in[0];
    const float* wq = (const float*)d_in[1];
    const float* bq = (const float*)d_in[2];
    const float* wk = (const float*)d_in[3];
    const float* bk = (const float*)d_in[4];
    const float* wv = (const float*)d_in[5];
    const float* bv = (const float*)d_in[6];
    const float* wo = (const float*)d_in[7];
    const float* bo = (const float*)d_in[8];
    float* out = (float*)d_out;

    float *q, *k, *v, *ctx, *xr, *wr;
    cudaGetSymbolAddress((void**)&q,   g_q);
    cudaGetSymbolAddress((void**)&k,   g_k);
    cudaGetSymbolAddress((void**)&v,   g_v);
    cudaGetSymbolAddress((void**)&ctx, g_ctx);
    cudaGetSymbolAddress((void**)&xr,  g_xr);
    cudaGetSymbolAddress((void**)&wr,  g_wr);

    cudaFuncSetAttribute(attn_mma, cudaFuncAttributeMaxDynamicSharedMemorySize, SMEM_ATTN);

    const dim3 ggrid(D_ / 128, M_ / 128);        // (16, 64)
    const int XB = (M_ * D_) / 4 / 256;
    const int WB = (D_ * D_) / 4 / 256;

    rope_table_kernel<<<(S_ * 64) / 256, 256>>>();
    preround_kernel<<<XB, 256>>>(x, xr);

    preround_kernel<<<WB, 256>>>(wq, wr);
    gemm_tf32<1><<<ggrid, 128>>>(xr, wr, bq, q);
    preround_kernel<<<WB, 256>>>(wk, wr);
    gemm_tf32<1><<<ggrid, 128>>>(xr, wr, bk, k);
    preround_kernel<<<WB, 256>>>(wv, wr);
    gemm_tf32<2><<<ggrid, 128>>>(xr, wr, bv, v);   // V transposed + tf32

    rope_k_kernel<<<(B_ * H_ * S_ * 64) / 256, 256>>>();  // g_k -> g_xr (roped)

    attn_mma<<<dim3(S_ / 128, B_ * H_), 256, SMEM_ATTN>>>(ctx);

    preround_kernel<<<WB, 256>>>(wo, wr);
    gemm_tf32<0><<<ggrid, 128>>>(ctx, wr, bo, out);
}

// round 13
// speedup vs baseline: 2.2881x; 1.1157x over previous
#include <cuda_runtime.h>
#include <math.h>
#include <stdint.h>

#define B_  4
#define S_  2048
#define D_  2048
#define H_  16
#define DH_ 128
#define M_  (B_*S_)

// Scratch (allowed: __device__ globals)
__device__ float g_q[(size_t)B_*H_*S_*DH_];    // Q [bh][s][dh]  (unroped)
__device__ float g_k[(size_t)B_*H_*S_*DH_];    // K [bh][s][dh]  (unroped)
__device__ float g_v[(size_t)B_*H_*S_*DH_];    // V [bh][dh][s]  (TRANSPOSED, tf32)
__device__ float g_ctx[(size_t)B_*S_*D_];
__device__ float g_xr[(size_t)M_*D_];          // tf32 x; later reused as roped-K
__device__ float g_wr[(size_t)D_*D_];          // tf32 weight (reused per GEMM)
__device__ float g_cos[(size_t)S_*64];
__device__ float g_sin[(size_t)S_*64];

// ---------------------------------------------------------------------------
// Helpers
// ---------------------------------------------------------------------------
__device__ __forceinline__ uint32_t tf32u(float x) {
    uint32_t r;
    asm("cvt.rna.tf32.f32 %0, %1;" : "=r"(r) : "f"(x));
    return r;
}
__device__ __forceinline__ float f2tf32(float x) { return __uint_as_float(tf32u(x)); }

__device__ __forceinline__ void mma_tf32(float c[4], const uint32_t a[4], const uint32_t b[2]) {
    asm volatile(
        "mma.sync.aligned.m16n8k8.row.col.f32.tf32.tf32.f32 "
        "{%0,%1,%2,%3}, {%4,%5,%6,%7}, {%8,%9}, {%0,%1,%2,%3};"
        : "+f"(c[0]), "+f"(c[1]), "+f"(c[2]), "+f"(c[3])
        : "r"(a[0]), "r"(a[1]), "r"(a[2]), "r"(a[3]), "r"(b[0]), "r"(b[1]));
}

__device__ __forceinline__ void cp16(uint32_t dst, const void* src) {
    asm volatile("cp.async.cg.shared.global [%0], [%1], 16;" :: "r"(dst), "l"(src));
}

// ---------------------------------------------------------------------------
// Pre-round: out[i] = tf32(in[i])
// ---------------------------------------------------------------------------
__global__ __launch_bounds__(256)
void preround_kernel(const float* __restrict__ in, float* __restrict__ out)
{
    const int i = blockIdx.x * blockDim.x + threadIdx.x;
    float4 v = ((const float4*)in)[i];
    v.x = f2tf32(v.x); v.y = f2tf32(v.y);
    v.z = f2tf32(v.z); v.w = f2tf32(v.w);
    ((float4*)out)[i] = v;
}

// ---------------------------------------------------------------------------
// TF32 GEMM: BK=32, 2-stage cp.async double buffer. C = A·Wᵀ + bias.
// A, W must be PRE-ROUNDED tf32. 128x128 block, 4 warps (2x2), 64x64 warp
// tile. Smem rows stride 36 -> fragment LDS conflict-free.
// OUT: 0=flat, 1=heads [bh][s][dh], 2=heads transposed [bh][dh][s] + tf32.
// ---------------------------------------------------------------------------
#define GBK 32

template<int OUT>
__global__ __launch_bounds__(128)
void gemm_tf32(const float* __restrict__ A, const float* __restrict__ W,
               const float* __restrict__ bias, float* __restrict__ C)
{
    __shared__ float As[2][128][36];
    __shared__ float Ws[2][128][36];
    const int K  = D_;
    const int m0 = blockIdx.y * 128;
    const int n0 = blockIdx.x * 128;
    const int tid  = threadIdx.x;
    const int warp = tid >> 5, lane = tid & 31;
    const int wy = warp >> 1, wx = warp & 1;
    const int lr = lane >> 2, lc = lane & 3;

    float acc[4][8][4];
#pragma unroll
    for (int ti = 0; ti < 4; ti++)
#pragma unroll
        for (int nt = 0; nt < 8; nt++)
#pragma unroll
            for (int e = 0; e < 4; e++) acc[ti][nt][e] = 0.f;

    // stage fill: 128 rows x 8 16B-chunks each for A and W
    auto issue = [&](int st, int k0) {
#pragma unroll
        for (int u = 0; u < 8; u++) {
            const int f = tid + u * 128;
            const int r = f >> 3, c4 = f & 7;
            cp16((uint32_t)__cvta_generic_to_shared(&As[st][r][c4 * 4]),
                 A + (size_t)(m0 + r) * K + k0 + c4 * 4);
        }
#pragma unroll
        for (int u = 0; u < 8; u++) {
            const int f = tid + u * 128;
            const int r = f >> 3, c4 = f & 7;
            cp16((uint32_t)__cvta_generic_to_shared(&Ws[st][r][c4 * 4]),
                 W + (size_t)(n0 + r) * K + k0 + c4 * 4);
        }
        asm volatile("cp.async.commit_group;");
    };

    issue(0, 0);

    const int NIT = K / GBK;                    // 64
#pragma unroll 1
    for (int it = 0; it < NIT; it++) {
        asm volatile("cp.async.wait_group 0;");
        __syncthreads();                         // all warps done with prev buffer
        if (it + 1 < NIT) issue((it + 1) & 1, (it + 1) * GBK);
        const int cur = it & 1;

#pragma unroll
        for (int kk = 0; kk < GBK; kk += 8) {
            uint32_t afr[4][4], bfr[8][2];
            const int ac = kk + lc;
#pragma unroll
            for (int ti = 0; ti < 4; ti++) {
                const int ar = wy * 64 + ti * 16 + lr;
                afr[ti][0] = __float_as_uint(As[cur][ar    ][ac]);
                afr[ti][1] = __float_as_uint(As[cur][ar + 8][ac]);
                afr[ti][2] = __float_as_uint(As[cur][ar    ][ac + 4]);
                afr[ti][3] = __float_as_uint(As[cur][ar + 8][ac + 4]);
            }
#pragma unroll
            for (int nt = 0; nt < 8; nt++) {
                const int br = wx * 64 + nt * 8 + lr;
                bfr[nt][0] = __float_as_uint(Ws[cur][br][ac]);
                bfr[nt][1] = __float_as_uint(Ws[cur][br][ac + 4]);
            }
#pragma unroll
            for (int ti = 0; ti < 4; ti++)
#pragma unroll
                for (int nt = 0; nt < 8; nt++)
                    mma_tf32(acc[ti][nt], afr[ti], bfr[nt]);
        }
    }

#pragma unroll
    for (int ti = 0; ti < 4; ti++) {
#pragma unroll
        for (int nt = 0; nt < 8; nt++) {
            const int row = m0 + wy * 64 + ti * 16 + lr;
            const int col = n0 + wx * 64 + nt * 8 + lc * 2;
#pragma unroll
            for (int e = 0; e < 4; e++) {
                const int m = row + (e >> 1) * 8;
                const int n = col + (e & 1);
                const float v = acc[ti][nt][e] + bias[n];
                if (OUT == 1) {
                    const int bb = m >> 11, s = m & (S_ - 1);
                    const int h = n >> 7, dh = n & 127;
                    C[(((size_t)bb * H_ + h) * S_ + s) * DH_ + dh] = v;
                } else if (OUT == 2) {
                    const int bb = m >> 11, s = m & (S_ - 1);
                    const int h = n >> 7, dh = n & 127;
                    C[(((size_t)(bb * H_ + h)) * DH_ + dh) * S_ + s] = f2tf32(v);
                } else {
                    C[(size_t)m * D_ + n] = v;
                }
            }
        }
    }
}

// ---------------------------------------------------------------------------
// RoPE table + K pre-rope (roped, tf32, into g_xr)
// ---------------------------------------------------------------------------
__global__ __launch_bounds__(256)
void rope_table_kernel()
{
    const int idx = blockIdx.x * blockDim.x + threadIdx.x;
    const int p = idx & 63;
    const int s = idx >> 6;
    const float invf = (float)exp(-(double)p * (log(10000.0) / 64.0));
    const float ang  = (float)s * invf;
    g_cos[idx] = (float)cos((double)ang);
    g_sin[idx] = (float)sin((double)ang);
}

__global__ __launch_bounds__(256)
void rope_k_kernel()
{
    const int idx = blockIdx.x * blockDim.x + threadIdx.x;  // B*H*S*64
    const int p   = idx & 63;
    const int row = idx >> 6;
    const int s   = row & (S_ - 1);
    const float cs = g_cos[s * 64 + p];
    const float sn = g_sin[s * 64 + p];
    const float* kb = g_k + (size_t)row * DH_;
    float* kr = g_xr + (size_t)row * DH_;
    const float k1 = kb[p], k2 = kb[p + 64];
    kr[p]      = f2tf32(k1 * cs - k2 * sn);
    kr[p + 64] = f2tf32(k2 * cs + k1 * sn);
}

// ---------------------------------------------------------------------------
// TF32 flash attention v3 (R11-proven): 256 threads / 8 warps, 128 q-rows
// per CTA, 64-key KV tiles double-buffered via cp.async from pre-roped K
// (g_xr) and transposed V (g_v).
// ---------------------------------------------------------------------------
#define KPAD 132
#define VPAD 68
#define PPAD 76
#define SMEM_ATTN ((128*KPAD + 2*128*VPAD + 128*PPAD) * 4)

__global__ __launch_bounds__(256)
void attn_mma(float* __restrict__ ctx)
{
    extern __shared__ float sm[];
    float* KB = sm;                        // 128*KPAD (2 x 64-row buffers)
    float* VB = sm + 128 * KPAD;           // 2 x 128*VPAD
    float* Ps = VB + 2 * 128 * VPAD;       // 128*PPAD

    const int bh  = blockIdx.y;
    const int m0  = blockIdx.x * 128;
    const int tid = threadIdx.x;
    const int warp = tid >> 5, lane = tid & 31;
    const int lr = lane >> 2, lc = lane & 3;
    const int qr = warp * 16;

    const float* Qb = g_q  + (size_t)bh * S_ * DH_;
    const float* Kr = g_xr + (size_t)bh * S_ * DH_;       // roped, tf32
    const float* Vt = g_v  + (size_t)bh * DH_ * S_;       // [dh][s], tf32

    const float scale = 0.08838834764831845f;   // 1/sqrt(128)

    // ---- stage Q with fused rope, scaled, tf32, into KB ----
#pragma unroll
    for (int i = 0; i < 8; i++) {
        const int idx = tid + i * 256;      // 128 rows x 16 pair-chunks
        const int r  = idx >> 4;
        const int p4 = idx & 15;
        const int s  = m0 + r;
        const float4 v1 = *(const float4*)(Qb + (size_t)s * DH_ + p4 * 4);
        const float4 v2 = *(const float4*)(Qb + (size_t)s * DH_ + p4 * 4 + 64);
        const float4 cs = *(const float4*)(g_cos + s * 64 + p4 * 4);
        const float4 sn = *(const float4*)(g_sin + s * 64 + p4 * 4);
        float4 o1, o2;
        o1.x = f2tf32((v1.x * cs.x - v2.x * sn.x) * scale);
        o1.y = f2tf32((v1.y * cs.y - v2.y * sn.y) * scale);
        o1.z = f2tf32((v1.z * cs.z - v2.z * sn.z) * scale);
        o1.w = f2tf32((v1.w * cs.w - v2.w * sn.w) * scale);
        o2.x = f2tf32((v2.x * cs.x + v1.x * sn.x) * scale);
        o2.y = f2tf32((v2.y * cs.y + v1.y * sn.y) * scale);
        o2.z = f2tf32((v2.z * cs.z + v1.z * sn.z) * scale);
        o2.w = f2tf32((v2.w * cs.w + v1.w * sn.w) * scale);
        *(float4*)(&KB[r * KPAD + p4 * 4])      = o1;
        *(float4*)(&KB[r * KPAD + p4 * 4 + 64]) = o2;
    }
    __syncthreads();
    uint32_t qf[16][4];
#pragma unroll
    for (int ks = 0; ks < 16; ks++) {
        qf[ks][0] = __float_as_uint(KB[(qr + lr    ) * KPAD + ks * 8 + lc    ]);
        qf[ks][1] = __float_as_uint(KB[(qr + lr + 8) * KPAD + ks * 8 + lc    ]);
        qf[ks][2] = __float_as_uint(KB[(qr + lr    ) * KPAD + ks * 8 + lc + 4]);
        qf[ks][3] = __float_as_uint(KB[(qr + lr + 8) * KPAD + ks * 8 + lc + 4]);
    }
    __syncthreads();   // Q fully consumed before K tiles overwrite KB

    auto issue_tile = [&](int t) {
        const int buf = t & 1;
        const int key0 = t * 64;
        float* kb = KB + buf * 64 * KPAD;
        float* vb = VB + buf * 128 * VPAD;
#pragma unroll
        for (int u = 0; u < 8; u++) {
            const int c = tid + u * 256;
            const int r = c >> 5, c4 = c & 31;
            cp16((uint32_t)__cvta_generic_to_shared(&kb[r * KPAD + c4 * 4]),
                 Kr + (size_t)(key0 + r) * DH_ + c4 * 4);
        }
#pragma unroll
        for (int u = 0; u < 8; u++) {
            const int c = tid + u * 256;
            const int r = c >> 4, c4 = c & 15;
            cp16((uint32_t)__cvta_generic_to_shared(&vb[r * VPAD + c4 * 4]),
                 Vt + (size_t)r * S_ + key0 + c4 * 4);
        }
        asm volatile("cp.async.commit_group;");
    };

    issue_tile(0);
    issue_tile(1);

    float oacc[16][4];
#pragma unroll
    for (int nt = 0; nt < 16; nt++)
#pragma unroll
        for (int e = 0; e < 4; e++) oacc[nt][e] = 0.f;
    float mr0 = -1e30f, mr1 = -1e30f, lsum0 = 0.f, lsum1 = 0.f;

#pragma unroll 1
    for (int kt = 0; kt < 32; kt++) {
        asm volatile("cp.async.wait_group %0;" :: "n"(1));
        __syncthreads();
        const int buf = kt & 1;
        const float* kb = KB + buf * 64 * KPAD;
        const float* vb = VB + buf * 128 * VPAD;

        float sacc[8][4];
#pragma unroll
        for (int n = 0; n < 8; n++)
#pragma unroll
            for (int e = 0; e < 4; e++) sacc[n][e] = 0.f;
#pragma unroll
        for (int ks = 0; ks < 16; ks++) {
#pragma unroll
            for (int n = 0; n < 8; n++) {
                uint32_t b[2];
                b[0] = __float_as_uint(kb[(n * 8 + lr) * KPAD + ks * 8 + lc    ]);
                b[1] = __float_as_uint(kb[(n * 8 + lr) * KPAD + ks * 8 + lc + 4]);
                mma_tf32(sacc[n], qf[ks], b);
            }
        }

        float mx0 = mr0, mx1 = mr1;
#pragma unroll
        for (int n = 0; n < 8; n++) {
            mx0 = fmaxf(mx0, fmaxf(sacc[n][0], sacc[n][1]));
            mx1 = fmaxf(mx1, fmaxf(sacc[n][2], sacc[n][3]));
        }
        mx0 = fmaxf(mx0, __shfl_xor_sync(0xffffffffu, mx0, 1));
        mx0 = fmaxf(mx0, __shfl_xor_sync(0xffffffffu, mx0, 2));
        mx1 = fmaxf(mx1, __shfl_xor_sync(0xffffffffu, mx1, 1));
        mx1 = fmaxf(mx1, __shfl_xor_sync(0xffffffffu, mx1, 2));
        const float f0 = __expf(mr0 - mx0);
        const float f1 = __expf(mr1 - mx1);
        mr0 = mx0; mr1 = mx1;

        float s0 = 0.f, s1 = 0.f;
#pragma unroll
        for (int n = 0; n < 8; n++) {
            const float p0 = __expf(sacc[n][0] - mx0);
            const float p1 = __expf(sacc[n][1] - mx0);
            const float p2 = __expf(sacc[n][2] - mx1);
            const float p3 = __expf(sacc[n][3] - mx1);
            s0 += p0 + p1; s1 += p2 + p3;
            float2 lo; lo.x = f2tf32(p0); lo.y = f2tf32(p1);
            *(float2*)(&Ps[(qr + lr    ) * PPAD + n * 8 + lc * 2]) = lo;
            float2 hi; hi.x = f2tf32(p2); hi.y = f2tf32(p3);
            *(float2*)(&Ps[(qr + lr + 8) * PPAD + n * 8 + lc * 2]) = hi;
        }
        s0 += __shfl_xor_sync(0xffffffffu, s0, 1);
        s0 += __shfl_xor_sync(0xffffffffu, s0, 2);
        s1 += __shfl_xor_sync(0xffffffffu, s1, 1);
        s1 += __shfl_xor_sync(0xffffffffu, s1, 2);
        lsum0 = lsum0 * f0 + s0;
        lsum1 = lsum1 * f1 + s1;
#pragma unroll
        for (int nt = 0; nt < 16; nt++) {
            oacc[nt][0] *= f0; oacc[nt][1] *= f0;
            oacc[nt][2] *= f1; oacc[nt][3] *= f1;
        }
        __syncwarp();

#pragma unroll
        for (int kk = 0; kk < 8; kk++) {
            uint32_t af[4];
            af[0] = __float_as_uint(Ps[(qr + lr    ) * PPAD + kk * 8 + lc    ]);
            af[1] = __float_as_uint(Ps[(qr + lr + 8) * PPAD + kk * 8 + lc    ]);
            af[2] = __float_as_uint(Ps[(qr + lr    ) * PPAD + kk * 8 + lc + 4]);
            af[3] = __float_as_uint(Ps[(qr + lr + 8) * PPAD + kk * 8 + lc + 4]);
#pragma unroll
            for (int nt = 0; nt < 16; nt++) {
                uint32_t b[2];
                b[0] = __float_as_uint(vb[(nt * 8 + lr) * VPAD + kk * 8 + lc    ]);
                b[1] = __float_as_uint(vb[(nt * 8 + lr) * VPAD + kk * 8 + lc + 4]);
                mma_tf32(oacc[nt], af, b);
            }
        }

        __syncthreads();
        if (kt + 2 < 32) {
            issue_tile(kt + 2);
        } else {
            asm volatile("cp.async.commit_group;");
        }
    }

    const float i0 = 1.f / lsum0, i1 = 1.f / lsum1;
    const int bb = bh >> 4, h = bh & 15;
    const int gr0 = m0 + qr + lr;
    float* o0 = ctx + ((size_t)bb * S_ + gr0) * D_ + h * DH_;
    float* o1 = o0 + (size_t)8 * D_;
#pragma unroll
    for (int nt = 0; nt < 16; nt++) {
        float2 a; a.x = f2tf32(oacc[nt][0] * i0); a.y = f2tf32(oacc[nt][1] * i0);
        *(float2*)(o0 + nt * 8 + lc * 2) = a;
        float2 b; b.x = f2tf32(oacc[nt][2] * i1); b.y = f2tf32(oacc[nt][3] * i1);
        *(float2*)(o1 + nt * 8 + lc * 2) = b;
    }
}

// ---------------------------------------------------------------------------
extern "C" void kernel_launch(void* const* d_in, const int* in_sizes, int n_in,
                              void* d_out, int out_size)
{
    const float* x  = (const float*)d_in[0];
    const float* wq = (const float*)d_in[1];
    const float* bq = (const float*)d_in[2];
    const float* wk = (const float*)d_in[3];
    const float* bk = (const float*)d_in[4];
    const float* wv = (const float*)d_in[5];
    const float* bv = (const float*)d_in[6];
    const float* wo = (const float*)d_in[7];
    const float* bo = (const float*)d_in[8];
    float* out = (float*)d_out;

    float *q, *k, *v, *ctx, *xr, *wr;
    cudaGetSymbolAddress((void**)&q,   g_q);
    cudaGetSymbolAddress((void**)&k,   g_k);
    cudaGetSymbolAddress((void**)&v,   g_v);
    cudaGetSymbolAddress((void**)&ctx, g_ctx);
    cudaGetSymbolAddress((void**)&xr,  g_xr);
    cudaGetSymbolAddress((void**)&wr,  g_wr);

    cudaFuncSetAttribute(attn_mma, cudaFuncAttributeMaxDynamicSharedMemorySize, SMEM_ATTN);

    const dim3 ggrid(D_ / 128, M_ / 128);        // (16, 64)
    const int XB = (M_ * D_) / 4 / 256;
    const int WB = (D_ * D_) / 4 / 256;

    rope_table_kernel<<<(S_ * 64) / 256, 256>>>();
    preround_kernel<<<XB, 256>>>(x, xr);

    preround_kernel<<<WB, 256>>>(wq, wr);
    gemm_tf32<1><<<ggrid, 128>>>(xr, wr, bq, q);
    preround_kernel<<<WB, 256>>>(wk, wr);
    gemm_tf32<1><<<ggrid, 128>>>(xr, wr, bk, k);
    preround_kernel<<<WB, 256>>>(wv, wr);
    gemm_tf32<2><<<ggrid, 128>>>(xr, wr, bv, v);   // V transposed + tf32

    rope_k_kernel<<<(B_ * H_ * S_ * 64) / 256, 256>>>();  // g_k -> g_xr (roped)

    attn_mma<<<dim3(S_ / 128, B_ * H_), 256, SMEM_ATTN>>>(ctx);

    preround_kernel<<<WB, 256>>>(wo, wr);
    gemm_tf32<0><<<ggrid, 128>>>(ctx, wr, bo, out);
}